// round 4
// baseline (speedup 1.0000x reference)
#include <cuda_runtime.h>
#include <math.h>

// ---------------- problem constants (match setup_inputs) ----------------
#define BATCH  2
#define TSEQ   2048
#define CDIM   1024
#define VDIM   8192
#define LAYERS 2
#define NHEAD  16
#define HD     64            // CDIM / NHEAD
#define BT     (BATCH * TSEQ)   // 4096 rows

// ---------------- scratch (device globals: allocation-free) -------------
__device__ float g_h[BT * CDIM];      // hidden state  [B*T, C]
__device__ float g_q[BT * CDIM];
__device__ float g_k[BT * CDIM];
__device__ float g_v[BT * CDIM];
__device__ float g_ctx[BT * CDIM];
__device__ float g_logits[(size_t)BT * VDIM];  // fallback if d_out can't hold logits
__device__ float g_nll[BT];

// ---------------- embedding + positional ----------------
__global__ void embed_kernel(const int* __restrict__ x,
                             const float* __restrict__ embed_w,
                             const float* __restrict__ pos) {
    size_t i = (size_t)blockIdx.x * blockDim.x + threadIdx.x;
    size_t total = (size_t)BT * CDIM;
    if (i >= total) return;
    int c  = (int)(i % CDIM);
    size_t bt = i / CDIM;
    int t  = (int)(bt % TSEQ);
    int tok = x[bt];
    g_h[i] = embed_w[(size_t)tok * CDIM + c] + pos[(size_t)t * CDIM + c];
}

// ---------------- NT GEMM: out[m,n] = sum_k A[m,k]*W[n,k] (+bias[n]) (+res[m,n]) ----
#define GBM 64
#define GBN 64
#define GBK 32

__global__ __launch_bounds__(256)
void gemm_nt_kernel(const float* __restrict__ A,   // [M,K] row-major
                    const float* __restrict__ W,   // [N,K] row-major
                    const float* __restrict__ bias, // [N] or null
                    const float* __restrict__ res,  // [M,N] or null
                    float* __restrict__ out,        // [M,N]
                    int M, int N, int K) {
    __shared__ float As[GBK][GBM + 4];
    __shared__ float Ws[GBK][GBN + 4];

    int tid = threadIdx.x;
    int tx = tid & 15;      // 0..15 -> n
    int ty = tid >> 4;      // 0..15 -> m
    int m0 = blockIdx.y * GBM;
    int n0 = blockIdx.x * GBN;

    float acc[4][4];
#pragma unroll
    for (int i = 0; i < 4; i++)
#pragma unroll
        for (int j = 0; j < 4; j++) acc[i][j] = 0.f;

    for (int k0 = 0; k0 < K; k0 += GBK) {
        // load 64x32 tiles of A and W (float4, fully in-bounds: dims are multiples)
#pragma unroll
        for (int it = 0; it < 2; it++) {
            int t = tid + it * 256;
            int r  = t >> 3;            // 0..63
            int c4 = (t & 7) << 2;      // 0,4,...,28
            float4 av = *(const float4*)&A[(size_t)(m0 + r) * K + k0 + c4];
            As[c4 + 0][r] = av.x; As[c4 + 1][r] = av.y;
            As[c4 + 2][r] = av.z; As[c4 + 3][r] = av.w;
            float4 wv = *(const float4*)&W[(size_t)(n0 + r) * K + k0 + c4];
            Ws[c4 + 0][r] = wv.x; Ws[c4 + 1][r] = wv.y;
            Ws[c4 + 2][r] = wv.z; Ws[c4 + 3][r] = wv.w;
        }
        __syncthreads();

#pragma unroll
        for (int k = 0; k < GBK; k++) {
            float4 af = *(const float4*)&As[k][ty << 2];
            float4 wf = *(const float4*)&Ws[k][tx << 2];
            float a[4] = {af.x, af.y, af.z, af.w};
            float w[4] = {wf.x, wf.y, wf.z, wf.w};
#pragma unroll
            for (int i = 0; i < 4; i++)
#pragma unroll
                for (int j = 0; j < 4; j++)
                    acc[i][j] = fmaf(a[i], w[j], acc[i][j]);
        }
        __syncthreads();
    }

#pragma unroll
    for (int i = 0; i < 4; i++) {
        int m = m0 + (ty << 2) + i;
#pragma unroll
        for (int j = 0; j < 4; j++) {
            int n = n0 + (tx << 2) + j;
            float v = acc[i][j];
            if (bias) v += bias[n];
            if (res)  v += res[(size_t)m * N + n];
            out[(size_t)m * N + n] = v;
        }
    }
}

// ---------------- causal attention (flash-style, online softmax) --------
// grid: (TSEQ/128, BATCH*NHEAD), block: 128 threads, 1 thread = 1 query row
__global__ __launch_bounds__(128)
void attn_kernel() {
    __shared__ float Ks[64][65];
    __shared__ float Vs[64][65];

    int bh = blockIdx.y;
    int b  = bh / NHEAD;
    int hh = bh % NHEAD;
    int qi = blockIdx.x * 128 + threadIdx.x;   // global query index in [0,T)

    const float* qp = g_q + ((size_t)(b * TSEQ + qi)) * CDIM + hh * HD;
    float qreg[HD];
#pragma unroll
    for (int i = 0; i < HD / 4; i++) {
        float4 t = *(const float4*)(qp + 4 * i);
        qreg[4*i+0] = t.x * 0.125f;   // fold in 1/sqrt(64)
        qreg[4*i+1] = t.y * 0.125f;
        qreg[4*i+2] = t.z * 0.125f;
        qreg[4*i+3] = t.w * 0.125f;
    }

    float o[HD];
#pragma unroll
    for (int i = 0; i < HD; i++) o[i] = 0.f;
    float mmax = -1e30f;
    float lsum = 0.f;

    int jend = (blockIdx.x + 1) * 128;    // uniform across block
    for (int j0 = 0; j0 < jend; j0 += 64) {
        __syncthreads();
        // cooperative load of K,V tiles: 64 rows x 64 dims
        for (int i = threadIdx.x; i < 64 * 16; i += 128) {
            int r  = i >> 4;
            int c4 = (i & 15) << 2;
            size_t base = ((size_t)(b * TSEQ + j0 + r)) * CDIM + hh * HD + c4;
            float4 kk = *(const float4*)&g_k[base];
            Ks[r][c4+0] = kk.x; Ks[r][c4+1] = kk.y; Ks[r][c4+2] = kk.z; Ks[r][c4+3] = kk.w;
            float4 vv = *(const float4*)&g_v[base];
            Vs[r][c4+0] = vv.x; Vs[r][c4+1] = vv.y; Vs[r][c4+2] = vv.z; Vs[r][c4+3] = vv.w;
        }
        __syncthreads();

        int jmax = qi - j0 + 1;           // causal: keys <= qi
        if (jmax > 64) jmax = 64;
        for (int j = 0; j < jmax; j++) {
            float s0 = 0.f, s1 = 0.f, s2 = 0.f, s3 = 0.f;
#pragma unroll
            for (int dd = 0; dd < HD; dd += 4) {
                s0 = fmaf(qreg[dd+0], Ks[j][dd+0], s0);
                s1 = fmaf(qreg[dd+1], Ks[j][dd+1], s1);
                s2 = fmaf(qreg[dd+2], Ks[j][dd+2], s2);
                s3 = fmaf(qreg[dd+3], Ks[j][dd+3], s3);
            }
            float s = (s0 + s1) + (s2 + s3);
            if (s > mmax) {
                float corr = __expf(mmax - s);
                lsum *= corr;
#pragma unroll
                for (int dd = 0; dd < HD; dd++) o[dd] *= corr;
                mmax = s;
            }
            float p = __expf(s - mmax);
            lsum += p;
#pragma unroll
            for (int dd = 0; dd < HD; dd++)
                o[dd] = fmaf(p, Vs[j][dd], o[dd]);
        }
    }

    float inv = 1.0f / lsum;
    float* cp = g_ctx + ((size_t)(b * TSEQ + qi)) * CDIM + hh * HD;
#pragma unroll
    for (int dd = 0; dd < HD; dd++) cp[dd] = o[dd] * inv;
}

// ---------------- log-softmax NLL per row --------------------------------
__global__ __launch_bounds__(256)
void loss_kernel(const float* __restrict__ logits, const int* __restrict__ target) {
    __shared__ float sm[256];
    int row = blockIdx.x;
    const float* lr = logits + (size_t)row * VDIM;
    int tid = threadIdx.x;

    float mx = -1e30f;
    for (int i = tid; i < VDIM; i += 256) mx = fmaxf(mx, lr[i]);
    sm[tid] = mx; __syncthreads();
    for (int s = 128; s > 0; s >>= 1) {
        if (tid < s) sm[tid] = fmaxf(sm[tid], sm[tid + s]);
        __syncthreads();
    }
    mx = sm[0]; __syncthreads();

    float se = 0.f;
    for (int i = tid; i < VDIM; i += 256) se += __expf(lr[i] - mx);
    sm[tid] = se; __syncthreads();
    for (int s = 128; s > 0; s >>= 1) {
        if (tid < s) sm[tid] += sm[tid + s];
        __syncthreads();
    }
    if (tid == 0)
        g_nll[row] = logf(sm[0]) + mx - lr[target[row]];
}

__global__ __launch_bounds__(1024)
void reduce_loss_kernel(float* __restrict__ out, long long loss_idx) {
    __shared__ float sm[1024];
    int tid = threadIdx.x;
    float s = 0.f;
    for (int i = tid; i < BT; i += 1024) s += g_nll[i];
    sm[tid] = s; __syncthreads();
    for (int st = 512; st > 0; st >>= 1) {
        if (tid < st) sm[tid] += sm[tid + st];
        __syncthreads();
    }
    if (tid == 0 && loss_idx >= 0)
        out[loss_idx] = sm[0] / (float)BT;
}

// ---------------- launch --------------------------------------------------
extern "C" void kernel_launch(void* const* d_in, const int* in_sizes, int n_in,
                              void* d_out, int out_size) {
    const int*   x      = (const int*)  d_in[0];
    const int*   target = (const int*)  d_in[1];
    const float* embed_w= (const float*)d_in[2];
    const float* pos    = (const float*)d_in[3];
    const float* Wq     = (const float*)d_in[4];
    const float* bq     = (const float*)d_in[5];
    const float* Wk     = (const float*)d_in[6];
    const float* bk     = (const float*)d_in[7];
    const float* Wv     = (const float*)d_in[8];
    const float* bv     = (const float*)d_in[9];
    const float* Wo     = (const float*)d_in[10];
    const float* bo     = (const float*)d_in[11];
    const float* Wu     = (const float*)d_in[12];
    float* out = (float*)d_out;

    float *h, *q, *k, *v, *ctx, *logits_scratch;
    cudaGetSymbolAddress((void**)&h,   g_h);
    cudaGetSymbolAddress((void**)&q,   g_q);
    cudaGetSymbolAddress((void**)&k,   g_k);
    cudaGetSymbolAddress((void**)&v,   g_v);
    cudaGetSymbolAddress((void**)&ctx, g_ctx);
    cudaGetSymbolAddress((void**)&logits_scratch, g_logits);

    const size_t nlogits = (size_t)BT * VDIM;
    float* logits_dst = ((size_t)out_size >= nlogits) ? out : logits_scratch;
    long long loss_idx;
    if ((size_t)out_size > nlogits)       loss_idx = (long long)nlogits; // logits + loss
    else if ((size_t)out_size < nlogits)  loss_idx = 0;                  // loss-only output
    else                                  loss_idx = -1;                 // logits-only output

    // 1) embedding + positional
    {
        size_t total = (size_t)BT * CDIM;
        embed_kernel<<<(unsigned)((total + 255) / 256), 256>>>(x, embed_w, pos);
    }

    // 2) transformer layers
    dim3 gqkv(CDIM / GBN, BT / GBM);     // (16, 64)
    for (int l = 0; l < LAYERS; l++) {
        const float* wq = Wq + (size_t)l * CDIM * CDIM;
        const float* wk = Wk + (size_t)l * CDIM * CDIM;
        const float* wv = Wv + (size_t)l * CDIM * CDIM;
        const float* wo = Wo + (size_t)l * CDIM * CDIM;
        gemm_nt_kernel<<<gqkv, 256>>>(h, wq, bq + l * CDIM, nullptr, q, BT, CDIM, CDIM);
        gemm_nt_kernel<<<gqkv, 256>>>(h, wk, bk + l * CDIM, nullptr, k, BT, CDIM, CDIM);
        gemm_nt_kernel<<<gqkv, 256>>>(h, wv, bv + l * CDIM, nullptr, v, BT, CDIM, CDIM);

        attn_kernel<<<dim3(TSEQ / 128, BATCH * NHEAD), 128>>>();

        // h = ctx @ Wo^T + bo + h   (residual fused)
        gemm_nt_kernel<<<gqkv, 256>>>(ctx, wo, bo + l * CDIM, h, h, BT, CDIM, CDIM);
    }

    // 3) logits = h @ Wu^T
    gemm_nt_kernel<<<dim3(VDIM / GBN, BT / GBM), 256>>>(h, Wu, nullptr, nullptr,
                                                        logits_dst, BT, VDIM, CDIM);

    // 4) loss
    loss_kernel<<<BT, 256>>>(logits_dst, target);
    reduce_loss_kernel<<<1, 1024>>>(out, loss_idx);
}

// round 6
// speedup vs baseline: 1.4834x; 1.4834x over previous
#include <cuda_runtime.h>
#include <cuda_bf16.h>
#include <stdint.h>
#include <math.h>

typedef unsigned int u32;

// ---------------- problem constants (match setup_inputs) ----------------
#define BATCH  2
#define TSEQ   2048
#define CDIM   1024
#define VDIM   8192
#define LAYERS 2
#define NHEAD  16
#define HD     64            // CDIM / NHEAD
#define BT     (BATCH * TSEQ)   // 4096 rows

// ---------------- scratch (device globals: allocation-free) -------------
__device__ float g_h[BT * CDIM];      // hidden state  [B*T, C]
__device__ float g_q[BT * CDIM];
__device__ float g_k[BT * CDIM];
__device__ float g_v[BT * CDIM];
__device__ float g_ctx[BT * CDIM];
__device__ float g_logits[(size_t)BT * VDIM];  // fallback if d_out can't hold logits
__device__ float g_nll[BT];

// bf16 hi/lo splits
__device__ __nv_bfloat16 g_ahi[BT * CDIM];
__device__ __nv_bfloat16 g_alo[BT * CDIM];
__device__ __nv_bfloat16 g_wqhi[LAYERS * CDIM * CDIM];
__device__ __nv_bfloat16 g_wqlo[LAYERS * CDIM * CDIM];
__device__ __nv_bfloat16 g_wkhi[LAYERS * CDIM * CDIM];
__device__ __nv_bfloat16 g_wklo[LAYERS * CDIM * CDIM];
__device__ __nv_bfloat16 g_wvhi[LAYERS * CDIM * CDIM];
__device__ __nv_bfloat16 g_wvlo[LAYERS * CDIM * CDIM];
__device__ __nv_bfloat16 g_wohi[LAYERS * CDIM * CDIM];
__device__ __nv_bfloat16 g_wolo[LAYERS * CDIM * CDIM];
__device__ __nv_bfloat16 g_wuhi[(size_t)VDIM * CDIM];
__device__ __nv_bfloat16 g_wulo[(size_t)VDIM * CDIM];

// ---------------- fp32 -> bf16 hi/lo split --------------------------------
__global__ void split_kernel(const float* __restrict__ src,
                             __nv_bfloat16* __restrict__ hi,
                             __nv_bfloat16* __restrict__ lo, size_t n) {
    size_t i = (size_t)blockIdx.x * blockDim.x + threadIdx.x;
    if (i >= n) return;
    float x = src[i];
    __nv_bfloat16 h = __float2bfloat16(x);
    hi[i] = h;
    lo[i] = __float2bfloat16(x - __bfloat162float(h));
}

// ---------------- embedding + positional ----------------
__global__ void embed_kernel(const int* __restrict__ x,
                             const float* __restrict__ embed_w,
                             const float* __restrict__ pos) {
    size_t i = (size_t)blockIdx.x * blockDim.x + threadIdx.x;
    size_t total = (size_t)BT * CDIM;
    if (i >= total) return;
    int c  = (int)(i % CDIM);
    size_t bt = i / CDIM;
    int t  = (int)(bt % TSEQ);
    int tok = x[bt];
    g_h[i] = embed_w[(size_t)tok * CDIM + c] + pos[(size_t)t * CDIM + c];
}

// ---------------- bf16x3 tensor-core GEMM ---------------------------------
// out[m,n] = sum_k A[m,k]*W[n,k] (+bias[n]) (+res[m,n]); A,W pre-split hi/lo bf16.
// Block tile 128(M) x 64(N) x 32(K); 8 warps, warp tile 64x16; mma m16n8k16.
#define GT 256

__device__ __forceinline__ void cp16(u32 s, const void* g) {
    asm volatile("cp.async.cg.shared.global [%0], [%1], 16;\n" :: "r"(s), "l"(g));
}
__device__ __forceinline__ void mma_bf16(float* d, const u32* a, const u32* b) {
    asm volatile(
        "mma.sync.aligned.m16n8k16.row.col.f32.bf16.bf16.f32 "
        "{%0,%1,%2,%3}, {%4,%5,%6,%7}, {%8,%9}, {%0,%1,%2,%3};\n"
        : "+f"(d[0]), "+f"(d[1]), "+f"(d[2]), "+f"(d[3])
        : "r"(a[0]), "r"(a[1]), "r"(a[2]), "r"(a[3]), "r"(b[0]), "r"(b[1]));
}

#define RS      80                      // padded row bytes (32 bf16 + 8 pad)
#define A_BYTES (128 * RS)              // 10240
#define B_BYTES (64 * RS)               // 5120
#define STAGE   (2 * A_BYTES + 2 * B_BYTES)   // 30720
#define GSMEM   (2 * STAGE)             // 61440

__global__ __launch_bounds__(GT, 2)
void gemm_bf16x3(const __nv_bfloat16* __restrict__ Ahi, const __nv_bfloat16* __restrict__ Alo,
                 const __nv_bfloat16* __restrict__ Whi, const __nv_bfloat16* __restrict__ Wlo,
                 const float* __restrict__ bias, const float* __restrict__ res,
                 float* __restrict__ out, int M, int N, int K) {
    extern __shared__ char smraw[];
    u32 sbase = (u32)__cvta_generic_to_shared(smraw);

    int tid = threadIdx.x;
    int lane = tid & 31, wid = tid >> 5;
    int warp_m = wid & 1;        // 2 -> 64 rows each
    int warp_n = wid >> 1;       // 4 -> 16 cols each
    int m0 = blockIdx.y * 128, n0 = blockIdx.x * 64;
    int qrow = lane >> 2;        // 0..7
    int qk2  = (lane & 3) * 2;   // 0,2,4,6

    float acc[4][2][4];
#pragma unroll
    for (int i = 0; i < 4; i++)
#pragma unroll
        for (int j = 0; j < 2; j++)
#pragma unroll
            for (int r = 0; r < 4; r++) acc[i][j][r] = 0.f;

    int NKB = K >> 5;

    // ---- async load of one stage ----
    auto issue_loads = [&](int kb, int s) {
        int kk = kb << 5;
        u32 st = sbase + s * STAGE;
#pragma unroll
        for (int ii = 0; ii < 6; ii++) {
            int i = tid + ii * GT;           // 0..1535
            if (i < 1024) {                  // A chunks: 512 hi + 512 lo
                const __nv_bfloat16* src = (i < 512) ? Ahi : Alo;
                int c = i & 511;
                int row = c >> 2, c16 = c & 3;
                u32 dst = st + ((i < 512) ? 0 : A_BYTES) + row * RS + c16 * 16;
                cp16(dst, src + (size_t)(m0 + row) * K + kk + c16 * 8);
            } else {                         // B chunks: 256 hi + 256 lo
                int j = i - 1024;
                const __nv_bfloat16* src = (j < 256) ? Whi : Wlo;
                int c = j & 255;
                int row = c >> 2, c16 = c & 3;
                u32 dst = st + 2 * A_BYTES + ((j < 256) ? 0 : B_BYTES) + row * RS + c16 * 16;
                cp16(dst, src + (size_t)(n0 + row) * K + kk + c16 * 8);
            }
        }
    };

    issue_loads(0, 0);
    asm volatile("cp.async.commit_group;\n");

    for (int kb = 0; kb < NKB; kb++) {
        if (kb + 1 < NKB) {
            issue_loads(kb + 1, (kb + 1) & 1);
            asm volatile("cp.async.commit_group;\n");
            asm volatile("cp.async.wait_group 1;\n");
        } else {
            asm volatile("cp.async.wait_group 0;\n");
        }
        __syncthreads();

        const char* st = smraw + (kb & 1) * STAGE;
        const char* As_hi = st;
        const char* As_lo = st + A_BYTES;
        const char* Bs_hi = st + 2 * A_BYTES;
        const char* Bs_lo = st + 2 * A_BYTES + B_BYTES;

#pragma unroll
        for (int ks = 0; ks < 2; ks++) {
            int kby = (ks * 16 + qk2) * 2;   // byte offset within padded row
            u32 ah[4][4], al[4][4], bh[2][2], bl[2][2];
#pragma unroll
            for (int mi = 0; mi < 4; mi++) {
                int r = warp_m * 64 + mi * 16 + qrow;
                ah[mi][0] = *(const u32*)(As_hi + r * RS + kby);
                ah[mi][1] = *(const u32*)(As_hi + (r + 8) * RS + kby);
                ah[mi][2] = *(const u32*)(As_hi + r * RS + kby + 16);
                ah[mi][3] = *(const u32*)(As_hi + (r + 8) * RS + kby + 16);
                al[mi][0] = *(const u32*)(As_lo + r * RS + kby);
                al[mi][1] = *(const u32*)(As_lo + (r + 8) * RS + kby);
                al[mi][2] = *(const u32*)(As_lo + r * RS + kby + 16);
                al[mi][3] = *(const u32*)(As_lo + (r + 8) * RS + kby + 16);
            }
#pragma unroll
            for (int ni = 0; ni < 2; ni++) {
                int r = warp_n * 16 + ni * 8 + qrow;
                bh[ni][0] = *(const u32*)(Bs_hi + r * RS + kby);
                bh[ni][1] = *(const u32*)(Bs_hi + r * RS + kby + 16);
                bl[ni][0] = *(const u32*)(Bs_lo + r * RS + kby);
                bl[ni][1] = *(const u32*)(Bs_lo + r * RS + kby + 16);
            }
#pragma unroll
            for (int mi = 0; mi < 4; mi++)
#pragma unroll
                for (int ni = 0; ni < 2; ni++) {
                    mma_bf16(acc[mi][ni], ah[mi], bh[ni]);
                    mma_bf16(acc[mi][ni], ah[mi], bl[ni]);
                    mma_bf16(acc[mi][ni], al[mi], bh[ni]);
                }
        }
        __syncthreads();
    }

    // ---- epilogue ----
#pragma unroll
    for (int mi = 0; mi < 4; mi++) {
        int r0 = m0 + warp_m * 64 + mi * 16 + qrow;
#pragma unroll
        for (int ni = 0; ni < 2; ni++) {
            int c = n0 + warp_n * 16 + ni * 8 + qk2;
            float v0 = acc[mi][ni][0], v1 = acc[mi][ni][1];
            float v2 = acc[mi][ni][2], v3 = acc[mi][ni][3];
            if (bias) { float b0 = bias[c], b1 = bias[c + 1]; v0 += b0; v1 += b1; v2 += b0; v3 += b1; }
            if (res) {
                v0 += res[(size_t)r0 * N + c];       v1 += res[(size_t)r0 * N + c + 1];
                v2 += res[(size_t)(r0 + 8) * N + c]; v3 += res[(size_t)(r0 + 8) * N + c + 1];
            }
            out[(size_t)r0 * N + c] = v0;       out[(size_t)r0 * N + c + 1] = v1;
            out[(size_t)(r0 + 8) * N + c] = v2; out[(size_t)(r0 + 8) * N + c + 1] = v3;
        }
    }
}

// ---------------- causal attention (flash-style, online softmax) --------
__global__ __launch_bounds__(128)
void attn_kernel() {
    __shared__ float Ks[64][65];
    __shared__ float Vs[64][65];

    int bh = blockIdx.y;
    int b  = bh / NHEAD;
    int hh = bh % NHEAD;
    int qi = blockIdx.x * 128 + threadIdx.x;

    const float* qp = g_q + ((size_t)(b * TSEQ + qi)) * CDIM + hh * HD;
    float qreg[HD];
#pragma unroll
    for (int i = 0; i < HD / 4; i++) {
        float4 t = *(const float4*)(qp + 4 * i);
        qreg[4*i+0] = t.x * 0.125f;
        qreg[4*i+1] = t.y * 0.125f;
        qreg[4*i+2] = t.z * 0.125f;
        qreg[4*i+3] = t.w * 0.125f;
    }

    float o[HD];
#pragma unroll
    for (int i = 0; i < HD; i++) o[i] = 0.f;
    float mmax = -1e30f;
    float lsum = 0.f;

    int jend = (blockIdx.x + 1) * 128;
    for (int j0 = 0; j0 < jend; j0 += 64) {
        __syncthreads();
        for (int i = threadIdx.x; i < 64 * 16; i += 128) {
            int r  = i >> 4;
            int c4 = (i & 15) << 2;
            size_t base = ((size_t)(b * TSEQ + j0 + r)) * CDIM + hh * HD + c4;
            float4 kk = *(const float4*)&g_k[base];
            Ks[r][c4+0] = kk.x; Ks[r][c4+1] = kk.y; Ks[r][c4+2] = kk.z; Ks[r][c4+3] = kk.w;
            float4 vv = *(const float4*)&g_v[base];
            Vs[r][c4+0] = vv.x; Vs[r][c4+1] = vv.y; Vs[r][c4+2] = vv.z; Vs[r][c4+3] = vv.w;
        }
        __syncthreads();

        int jmax = qi - j0 + 1;
        if (jmax > 64) jmax = 64;
        for (int j = 0; j < jmax; j++) {
            float s0 = 0.f, s1 = 0.f, s2 = 0.f, s3 = 0.f;
#pragma unroll
            for (int dd = 0; dd < HD; dd += 4) {
                s0 = fmaf(qreg[dd+0], Ks[j][dd+0], s0);
                s1 = fmaf(qreg[dd+1], Ks[j][dd+1], s1);
                s2 = fmaf(qreg[dd+2], Ks[j][dd+2], s2);
                s3 = fmaf(qreg[dd+3], Ks[j][dd+3], s3);
            }
            float s = (s0 + s1) + (s2 + s3);
            if (s > mmax) {
                float corr = __expf(mmax - s);
                lsum *= corr;
#pragma unroll
                for (int dd = 0; dd < HD; dd++) o[dd] *= corr;
                mmax = s;
            }
            float p = __expf(s - mmax);
            lsum += p;
#pragma unroll
            for (int dd = 0; dd < HD; dd++)
                o[dd] = fmaf(p, Vs[j][dd], o[dd]);
        }
    }

    float inv = 1.0f / lsum;
    float* cp = g_ctx + ((size_t)(b * TSEQ + qi)) * CDIM + hh * HD;
#pragma unroll
    for (int dd = 0; dd < HD; dd++) cp[dd] = o[dd] * inv;
}

// ---------------- log-softmax NLL per row --------------------------------
__global__ __launch_bounds__(256)
void loss_kernel(const float* __restrict__ logits, const int* __restrict__ target) {
    __shared__ float sm[256];
    int row = blockIdx.x;
    const float* lr = logits + (size_t)row * VDIM;
    int tid = threadIdx.x;

    float mx = -1e30f;
    for (int i = tid; i < VDIM; i += 256) mx = fmaxf(mx, lr[i]);
    sm[tid] = mx; __syncthreads();
    for (int s = 128; s > 0; s >>= 1) {
        if (tid < s) sm[tid] = fmaxf(sm[tid], sm[tid + s]);
        __syncthreads();
    }
    mx = sm[0]; __syncthreads();

    float se = 0.f;
    for (int i = tid; i < VDIM; i += 256) se += __expf(lr[i] - mx);
    sm[tid] = se; __syncthreads();
    for (int s = 128; s > 0; s >>= 1) {
        if (tid < s) sm[tid] += sm[tid + s];
        __syncthreads();
    }
    if (tid == 0)
        g_nll[row] = logf(sm[0]) + mx - lr[target[row]];
}

__global__ __launch_bounds__(1024)
void reduce_loss_kernel(float* __restrict__ out, long long loss_idx) {
    __shared__ float sm[1024];
    int tid = threadIdx.x;
    float s = 0.f;
    for (int i = tid; i < BT; i += 1024) s += g_nll[i];
    sm[tid] = s; __syncthreads();
    for (int st = 512; st > 0; st >>= 1) {
        if (tid < st) sm[tid] += sm[tid + st];
        __syncthreads();
    }
    if (tid == 0 && loss_idx >= 0)
        out[loss_idx] = sm[0] / (float)BT;
}

// ---------------- launch --------------------------------------------------
extern "C" void kernel_launch(void* const* d_in, const int* in_sizes, int n_in,
                              void* d_out, int out_size) {
    const int*   x      = (const int*)  d_in[0];
    const int*   target = (const int*)  d_in[1];
    const float* embed_w= (const float*)d_in[2];
    const float* pos    = (const float*)d_in[3];
    const float* Wq     = (const float*)d_in[4];
    const float* bq     = (const float*)d_in[5];
    const float* Wk     = (const float*)d_in[6];
    const float* bk     = (const float*)d_in[7];
    const float* Wv     = (const float*)d_in[8];
    const float* bv     = (const float*)d_in[9];
    const float* Wo     = (const float*)d_in[10];
    const float* bo     = (const float*)d_in[11];
    const float* Wu     = (const float*)d_in[12];
    float* out = (float*)d_out;

    float *h, *q, *k, *v, *ctx, *logits_scratch;
    cudaGetSymbolAddress((void**)&h,   g_h);
    cudaGetSymbolAddress((void**)&q,   g_q);
    cudaGetSymbolAddress((void**)&k,   g_k);
    cudaGetSymbolAddress((void**)&v,   g_v);
    cudaGetSymbolAddress((void**)&ctx, g_ctx);
    cudaGetSymbolAddress((void**)&logits_scratch, g_logits);

    __nv_bfloat16 *ahi, *alo, *wqhi, *wqlo, *wkhi, *wklo, *wvhi, *wvlo, *wohi, *wolo, *wuhi, *wulo;
    cudaGetSymbolAddress((void**)&ahi, g_ahi);
    cudaGetSymbolAddress((void**)&alo, g_alo);
    cudaGetSymbolAddress((void**)&wqhi, g_wqhi); cudaGetSymbolAddress((void**)&wqlo, g_wqlo);
    cudaGetSymbolAddress((void**)&wkhi, g_wkhi); cudaGetSymbolAddress((void**)&wklo, g_wklo);
    cudaGetSymbolAddress((void**)&wvhi, g_wvhi); cudaGetSymbolAddress((void**)&wvlo, g_wvlo);
    cudaGetSymbolAddress((void**)&wohi, g_wohi); cudaGetSymbolAddress((void**)&wolo, g_wolo);
    cudaGetSymbolAddress((void**)&wuhi, g_wuhi); cudaGetSymbolAddress((void**)&wulo, g_wulo);

    static bool attr_set = false;
    if (!attr_set) {
        cudaFuncSetAttribute(gemm_bf16x3, cudaFuncAttributeMaxDynamicSharedMemorySize, GSMEM);
        attr_set = true;
    }

    const size_t nlogits = (size_t)BT * VDIM;
    float* logits_dst = ((size_t)out_size >= nlogits) ? out : logits_scratch;
    long long loss_idx;
    if ((size_t)out_size > nlogits)       loss_idx = (long long)nlogits;
    else if ((size_t)out_size < nlogits)  loss_idx = 0;
    else                                  loss_idx = -1;

    // 0) weight splits
    {
        size_t nw = (size_t)LAYERS * CDIM * CDIM;
        unsigned gb = (unsigned)((nw + 255) / 256);
        split_kernel<<<gb, 256>>>(Wq, wqhi, wqlo, nw);
        split_kernel<<<gb, 256>>>(Wk, wkhi, wklo, nw);
        split_kernel<<<gb, 256>>>(Wv, wvhi, wvlo, nw);
        split_kernel<<<gb, 256>>>(Wo, wohi, wolo, nw);
        size_t nu = (size_t)VDIM * CDIM;
        split_kernel<<<(unsigned)((nu + 255) / 256), 256>>>(Wu, wuhi, wulo, nu);
    }

    // 1) embedding + positional
    {
        size_t total = (size_t)BT * CDIM;
        embed_kernel<<<(unsigned)((total + 255) / 256), 256>>>(x, embed_w, pos);
    }

    // 2) transformer layers
    const size_t nh = (size_t)BT * CDIM;
    unsigned gsplit = (unsigned)((nh + 255) / 256);
    dim3 gC(CDIM / 64, BT / 128);       // (16, 32)
    for (int l = 0; l < LAYERS; l++) {
        size_t woff = (size_t)l * CDIM * CDIM;
        split_kernel<<<gsplit, 256>>>(h, ahi, alo, nh);
        gemm_bf16x3<<<gC, GT, GSMEM>>>(ahi, alo, wqhi + woff, wqlo + woff,
                                       bq + l * CDIM, nullptr, q, BT, CDIM, CDIM);
        gemm_bf16x3<<<gC, GT, GSMEM>>>(ahi, alo, wkhi + woff, wklo + woff,
                                       bk + l * CDIM, nullptr, k, BT, CDIM, CDIM);
        gemm_bf16x3<<<gC, GT, GSMEM>>>(ahi, alo, wvhi + woff, wvlo + woff,
                                       bv + l * CDIM, nullptr, v, BT, CDIM, CDIM);

        attn_kernel<<<dim3(TSEQ / 128, BATCH * NHEAD), 128>>>();

        split_kernel<<<gsplit, 256>>>(ctx, ahi, alo, nh);
        gemm_bf16x3<<<gC, GT, GSMEM>>>(ahi, alo, wohi + woff, wolo + woff,
                                       bo + l * CDIM, h, h, BT, CDIM, CDIM);
    }

    // 3) logits = h @ Wu^T
    split_kernel<<<gsplit, 256>>>(h, ahi, alo, nh);
    gemm_bf16x3<<<dim3(VDIM / 64, BT / 128), GT, GSMEM>>>(ahi, alo, wuhi, wulo,
                                                          nullptr, nullptr,
                                                          logits_dst, BT, VDIM, CDIM);

    // 4) loss
    loss_kernel<<<BT, 256>>>(logits_dst, target);
    reduce_loss_kernel<<<1, 1024>>>(out, loss_idx);
}

// round 7
// speedup vs baseline: 2.7920x; 1.8822x over previous
#include <cuda_runtime.h>
#include <cuda_bf16.h>
#include <stdint.h>
#include <math.h>

typedef unsigned int u32;

// ---------------- problem constants (match setup_inputs) ----------------
#define BATCH  2
#define TSEQ   2048
#define CDIM   1024
#define VDIM   8192
#define LAYERS 2
#define NHEAD  16
#define HD     64            // CDIM / NHEAD
#define BT     (BATCH * TSEQ)   // 4096 rows

// ---------------- scratch (device globals: allocation-free) -------------
__device__ float g_h[BT * CDIM];      // hidden state  [B*T, C]
__device__ float g_q[BT * CDIM];
__device__ float g_k[BT * CDIM];
__device__ float g_v[BT * CDIM];
__device__ float g_ctx[BT * CDIM];
__device__ float g_logits[(size_t)BT * VDIM];  // fallback if d_out can't hold logits
__device__ float g_nll[BT];

// bf16 hi/lo splits
__device__ __nv_bfloat16 g_ahi[BT * CDIM];
__device__ __nv_bfloat16 g_alo[BT * CDIM];
__device__ __nv_bfloat16 g_wqhi[LAYERS * CDIM * CDIM];
__device__ __nv_bfloat16 g_wqlo[LAYERS * CDIM * CDIM];
__device__ __nv_bfloat16 g_wkhi[LAYERS * CDIM * CDIM];
__device__ __nv_bfloat16 g_wklo[LAYERS * CDIM * CDIM];
__device__ __nv_bfloat16 g_wvhi[LAYERS * CDIM * CDIM];
__device__ __nv_bfloat16 g_wvlo[LAYERS * CDIM * CDIM];
__device__ __nv_bfloat16 g_wohi[LAYERS * CDIM * CDIM];
__device__ __nv_bfloat16 g_wolo[LAYERS * CDIM * CDIM];
__device__ __nv_bfloat16 g_wuhi[(size_t)VDIM * CDIM];
__device__ __nv_bfloat16 g_wulo[(size_t)VDIM * CDIM];

// ---------------- fp32 -> bf16 hi/lo split --------------------------------
__global__ void split_kernel(const float* __restrict__ src,
                             __nv_bfloat16* __restrict__ hi,
                             __nv_bfloat16* __restrict__ lo, size_t n) {
    size_t i = (size_t)blockIdx.x * blockDim.x + threadIdx.x;
    if (i >= n) return;
    float x = src[i];
    __nv_bfloat16 h = __float2bfloat16(x);
    hi[i] = h;
    lo[i] = __float2bfloat16(x - __bfloat162float(h));
}

// ---------------- embedding + positional ----------------
__global__ void embed_kernel(const int* __restrict__ x,
                             const float* __restrict__ embed_w,
                             const float* __restrict__ pos) {
    size_t i = (size_t)blockIdx.x * blockDim.x + threadIdx.x;
    size_t total = (size_t)BT * CDIM;
    if (i >= total) return;
    int c  = (int)(i % CDIM);
    size_t bt = i / CDIM;
    int t  = (int)(bt % TSEQ);
    int tok = x[bt];
    g_h[i] = embed_w[(size_t)tok * CDIM + c] + pos[(size_t)t * CDIM + c];
}

// ---------------- shared MMA helpers --------------------------------------
__device__ __forceinline__ void cp16(u32 s, const void* g) {
    asm volatile("cp.async.cg.shared.global [%0], [%1], 16;\n" :: "r"(s), "l"(g));
}
__device__ __forceinline__ void mma_bf16(float* d, const u32* a, const u32* b) {
    asm volatile(
        "mma.sync.aligned.m16n8k16.row.col.f32.bf16.bf16.f32 "
        "{%0,%1,%2,%3}, {%4,%5,%6,%7}, {%8,%9}, {%0,%1,%2,%3};\n"
        : "+f"(d[0]), "+f"(d[1]), "+f"(d[2]), "+f"(d[3])
        : "r"(a[0]), "r"(a[1]), "r"(a[2]), "r"(a[3]), "r"(b[0]), "r"(b[1]));
}
__device__ __forceinline__ u32 pk2(float x, float y) {
    __nv_bfloat162 p = __floats2bfloat162_rn(x, y);
    return *(u32*)&p;
}

// ---------------- bf16x3 tensor-core GEMM ---------------------------------
#define GT 256
#define RS      80                      // padded row bytes (32 bf16 + 8 pad)
#define A_BYTES (128 * RS)              // 10240
#define B_BYTES (64 * RS)               // 5120
#define STAGE   (2 * A_BYTES + 2 * B_BYTES)   // 30720
#define GSMEM   (2 * STAGE)             // 61440

__global__ __launch_bounds__(GT, 2)
void gemm_bf16x3(const __nv_bfloat16* __restrict__ Ahi, const __nv_bfloat16* __restrict__ Alo,
                 const __nv_bfloat16* __restrict__ Whi, const __nv_bfloat16* __restrict__ Wlo,
                 const float* __restrict__ bias, const float* __restrict__ res,
                 float* __restrict__ out, int M, int N, int K) {
    extern __shared__ char smraw[];
    u32 sbase = (u32)__cvta_generic_to_shared(smraw);

    int tid = threadIdx.x;
    int lane = tid & 31, wid = tid >> 5;
    int warp_m = wid & 1;
    int warp_n = wid >> 1;
    int m0 = blockIdx.y * 128, n0 = blockIdx.x * 64;
    int qrow = lane >> 2;
    int qk2  = (lane & 3) * 2;

    float acc[4][2][4];
#pragma unroll
    for (int i = 0; i < 4; i++)
#pragma unroll
        for (int j = 0; j < 2; j++)
#pragma unroll
            for (int r = 0; r < 4; r++) acc[i][j][r] = 0.f;

    int NKB = K >> 5;

    auto issue_loads = [&](int kb, int s) {
        int kk = kb << 5;
        u32 st = sbase + s * STAGE;
#pragma unroll
        for (int ii = 0; ii < 6; ii++) {
            int i = tid + ii * GT;
            if (i < 1024) {
                const __nv_bfloat16* src = (i < 512) ? Ahi : Alo;
                int c = i & 511;
                int row = c >> 2, c16 = c & 3;
                u32 dst = st + ((i < 512) ? 0 : A_BYTES) + row * RS + c16 * 16;
                cp16(dst, src + (size_t)(m0 + row) * K + kk + c16 * 8);
            } else {
                int j = i - 1024;
                const __nv_bfloat16* src = (j < 256) ? Whi : Wlo;
                int c = j & 255;
                int row = c >> 2, c16 = c & 3;
                u32 dst = st + 2 * A_BYTES + ((j < 256) ? 0 : B_BYTES) + row * RS + c16 * 16;
                cp16(dst, src + (size_t)(n0 + row) * K + kk + c16 * 8);
            }
        }
    };

    issue_loads(0, 0);
    asm volatile("cp.async.commit_group;\n");

    for (int kb = 0; kb < NKB; kb++) {
        if (kb + 1 < NKB) {
            issue_loads(kb + 1, (kb + 1) & 1);
            asm volatile("cp.async.commit_group;\n");
            asm volatile("cp.async.wait_group 1;\n");
        } else {
            asm volatile("cp.async.wait_group 0;\n");
        }
        __syncthreads();

        const char* st = smraw + (kb & 1) * STAGE;
        const char* As_hi = st;
        const char* As_lo = st + A_BYTES;
        const char* Bs_hi = st + 2 * A_BYTES;
        const char* Bs_lo = st + 2 * A_BYTES + B_BYTES;

#pragma unroll
        for (int ks = 0; ks < 2; ks++) {
            int kby = (ks * 16 + qk2) * 2;
            u32 ah[4][4], al[4][4], bh[2][2], bl[2][2];
#pragma unroll
            for (int mi = 0; mi < 4; mi++) {
                int r = warp_m * 64 + mi * 16 + qrow;
                ah[mi][0] = *(const u32*)(As_hi + r * RS + kby);
                ah[mi][1] = *(const u32*)(As_hi + (r + 8) * RS + kby);
                ah[mi][2] = *(const u32*)(As_hi + r * RS + kby + 16);
                ah[mi][3] = *(const u32*)(As_hi + (r + 8) * RS + kby + 16);
                al[mi][0] = *(const u32*)(As_lo + r * RS + kby);
                al[mi][1] = *(const u32*)(As_lo + (r + 8) * RS + kby);
                al[mi][2] = *(const u32*)(As_lo + r * RS + kby + 16);
                al[mi][3] = *(const u32*)(As_lo + (r + 8) * RS + kby + 16);
            }
#pragma unroll
            for (int ni = 0; ni < 2; ni++) {
                int r = warp_n * 16 + ni * 8 + qrow;
                bh[ni][0] = *(const u32*)(Bs_hi + r * RS + kby);
                bh[ni][1] = *(const u32*)(Bs_hi + r * RS + kby + 16);
                bl[ni][0] = *(const u32*)(Bs_lo + r * RS + kby);
                bl[ni][1] = *(const u32*)(Bs_lo + r * RS + kby + 16);
            }
#pragma unroll
            for (int mi = 0; mi < 4; mi++)
#pragma unroll
                for (int ni = 0; ni < 2; ni++) {
                    mma_bf16(acc[mi][ni], ah[mi], bh[ni]);
                    mma_bf16(acc[mi][ni], ah[mi], bl[ni]);
                    mma_bf16(acc[mi][ni], al[mi], bh[ni]);
                }
        }
        __syncthreads();
    }

#pragma unroll
    for (int mi = 0; mi < 4; mi++) {
        int r0 = m0 + warp_m * 64 + mi * 16 + qrow;
#pragma unroll
        for (int ni = 0; ni < 2; ni++) {
            int c = n0 + warp_n * 16 + ni * 8 + qk2;
            float v0 = acc[mi][ni][0], v1 = acc[mi][ni][1];
            float v2 = acc[mi][ni][2], v3 = acc[mi][ni][3];
            if (bias) { float b0 = bias[c], b1 = bias[c + 1]; v0 += b0; v1 += b1; v2 += b0; v3 += b1; }
            if (res) {
                v0 += res[(size_t)r0 * N + c];       v1 += res[(size_t)r0 * N + c + 1];
                v2 += res[(size_t)(r0 + 8) * N + c]; v3 += res[(size_t)(r0 + 8) * N + c + 1];
            }
            out[(size_t)r0 * N + c] = v0;       out[(size_t)r0 * N + c + 1] = v1;
            out[(size_t)(r0 + 8) * N + c] = v2; out[(size_t)(r0 + 8) * N + c + 1] = v3;
        }
    }
}

// ---------------- MMA flash attention -------------------------------------
// CTA: 64 queries of one (b,h); 4 warps x 16 queries; KV tiles of 64 keys.
// bf16 hi/lo (3-pass) for both QK^T and PV; fp32 online softmax in registers.
#define APAD 72                     // bf16 row stride in SMEM tiles
#define ATSZ (64 * APAD)            // elements per tile array
#define ASMEM (6 * ATSZ * 2)        // 55296 bytes

__global__ __launch_bounds__(128)
void attn_mma_kernel() {
    extern __shared__ __nv_bfloat16 asmem[];
    __nv_bfloat16* Qh = asmem;
    __nv_bfloat16* Ql = Qh + ATSZ;
    __nv_bfloat16* Kh = Ql + ATSZ;
    __nv_bfloat16* Kl = Kh + ATSZ;
    __nv_bfloat16* Vh = Kl + ATSZ;   // transposed: Vh[d][key]
    __nv_bfloat16* Vl = Vh + ATSZ;

    int tid = threadIdx.x, lane = tid & 31, wq = tid >> 5;
    int g = lane >> 2, t = lane & 3;
    int bh = blockIdx.y, b = bh >> 4, hh = bh & 15;
    int qt = blockIdx.x;

    size_t qbase = ((size_t)(b * TSEQ + qt * 64)) * CDIM + hh * HD;

    // ---- load Q tile (fold 1/sqrt(d)=0.125), split hi/lo ----
    for (int i = tid; i < 64 * 16; i += 128) {
        int r = i >> 4, c4 = (i & 15) << 2;
        float4 qv = *(const float4*)&g_q[qbase + (size_t)r * CDIM + c4];
        float xs[4] = {qv.x * 0.125f, qv.y * 0.125f, qv.z * 0.125f, qv.w * 0.125f};
#pragma unroll
        for (int j = 0; j < 4; j++) {
            __nv_bfloat16 hb = __float2bfloat16(xs[j]);
            Qh[r * APAD + c4 + j] = hb;
            Ql[r * APAD + c4 + j] = __float2bfloat16(xs[j] - __bfloat162float(hb));
        }
    }
    __syncthreads();

    // ---- cache Q fragments in registers ----
    u32 qah[4][4], qal[4][4];
#pragma unroll
    for (int kb = 0; kb < 4; kb++) {
        int r = wq * 16 + g, kk = kb * 16 + t * 2;
        qah[kb][0] = *(const u32*)&Qh[r * APAD + kk];
        qah[kb][1] = *(const u32*)&Qh[(r + 8) * APAD + kk];
        qah[kb][2] = *(const u32*)&Qh[r * APAD + kk + 8];
        qah[kb][3] = *(const u32*)&Qh[(r + 8) * APAD + kk + 8];
        qal[kb][0] = *(const u32*)&Ql[r * APAD + kk];
        qal[kb][1] = *(const u32*)&Ql[(r + 8) * APAD + kk];
        qal[kb][2] = *(const u32*)&Ql[r * APAD + kk + 8];
        qal[kb][3] = *(const u32*)&Ql[(r + 8) * APAD + kk + 8];
    }

    float m0r = -1e30f, m1r = -1e30f, l0 = 0.f, l1 = 0.f;
    float o[8][4];
#pragma unroll
    for (int nt = 0; nt < 8; nt++)
#pragma unroll
        for (int i = 0; i < 4; i++) o[nt][i] = 0.f;

    for (int kt = 0; kt <= qt; kt++) {
        __syncthreads();   // previous tile's K/V no longer read
        size_t kbase = ((size_t)(b * TSEQ + kt * 64)) * CDIM + hh * HD;
        // ---- load + split K, load + split + transpose V ----
        for (int i = tid; i < 64 * 16; i += 128) {
            int r = i >> 4, c4 = (i & 15) << 2;
            size_t gb = kbase + (size_t)r * CDIM + c4;
            float4 kv = *(const float4*)&g_k[gb];
            float ks[4] = {kv.x, kv.y, kv.z, kv.w};
#pragma unroll
            for (int j = 0; j < 4; j++) {
                __nv_bfloat16 hb = __float2bfloat16(ks[j]);
                Kh[r * APAD + c4 + j] = hb;
                Kl[r * APAD + c4 + j] = __float2bfloat16(ks[j] - __bfloat162float(hb));
            }
            float4 vv = *(const float4*)&g_v[gb];
            float vs[4] = {vv.x, vv.y, vv.z, vv.w};
#pragma unroll
            for (int j = 0; j < 4; j++) {
                __nv_bfloat16 hb = __float2bfloat16(vs[j]);
                Vh[(c4 + j) * APAD + r] = hb;                // transpose
                Vl[(c4 + j) * APAD + r] = __float2bfloat16(vs[j] - __bfloat162float(hb));
            }
        }
        __syncthreads();

        // ---- S = Q K^T (3-pass bf16x3) ----
        float s[8][4];
#pragma unroll
        for (int nt = 0; nt < 8; nt++)
#pragma unroll
            for (int i = 0; i < 4; i++) s[nt][i] = 0.f;

#pragma unroll
        for (int nt = 0; nt < 8; nt++) {
#pragma unroll
            for (int kb = 0; kb < 4; kb++) {
                int off = (nt * 8 + g) * APAD + kb * 16 + t * 2;
                u32 bh2[2], bl2[2];
                bh2[0] = *(const u32*)&Kh[off];
                bh2[1] = *(const u32*)&Kh[off + 8];
                bl2[0] = *(const u32*)&Kl[off];
                bl2[1] = *(const u32*)&Kl[off + 8];
                mma_bf16(s[nt], qah[kb], bh2);
                mma_bf16(s[nt], qah[kb], bl2);
                mma_bf16(s[nt], qal[kb], bh2);
            }
        }

        // ---- causal mask (diagonal tile only) ----
        if (kt == qt) {
            int r0 = wq * 16 + g, r1 = r0 + 8;
#pragma unroll
            for (int nt = 0; nt < 8; nt++) {
                int c0 = nt * 8 + t * 2;
                if (c0 > r0)     s[nt][0] = -1e30f;
                if (c0 + 1 > r0) s[nt][1] = -1e30f;
                if (c0 > r1)     s[nt][2] = -1e30f;
                if (c0 + 1 > r1) s[nt][3] = -1e30f;
            }
        }

        // ---- online softmax ----
        float tm0 = -1e30f, tm1 = -1e30f;
#pragma unroll
        for (int nt = 0; nt < 8; nt++) {
            tm0 = fmaxf(tm0, fmaxf(s[nt][0], s[nt][1]));
            tm1 = fmaxf(tm1, fmaxf(s[nt][2], s[nt][3]));
        }
        tm0 = fmaxf(tm0, __shfl_xor_sync(0xffffffffu, tm0, 1));
        tm0 = fmaxf(tm0, __shfl_xor_sync(0xffffffffu, tm0, 2));
        tm1 = fmaxf(tm1, __shfl_xor_sync(0xffffffffu, tm1, 1));
        tm1 = fmaxf(tm1, __shfl_xor_sync(0xffffffffu, tm1, 2));

        float mn0 = fmaxf(m0r, tm0), mn1 = fmaxf(m1r, tm1);
        float cf0 = __expf(m0r - mn0), cf1 = __expf(m1r - mn1);
        l0 *= cf0; l1 *= cf1;
#pragma unroll
        for (int nt = 0; nt < 8; nt++) {
            o[nt][0] *= cf0; o[nt][1] *= cf0;
            o[nt][2] *= cf1; o[nt][3] *= cf1;
        }
        m0r = mn0; m1r = mn1;

        float rs0 = 0.f, rs1 = 0.f;
#pragma unroll
        for (int nt = 0; nt < 8; nt++) {
            s[nt][0] = __expf(s[nt][0] - mn0);
            s[nt][1] = __expf(s[nt][1] - mn0);
            s[nt][2] = __expf(s[nt][2] - mn1);
            s[nt][3] = __expf(s[nt][3] - mn1);
            rs0 += s[nt][0] + s[nt][1];
            rs1 += s[nt][2] + s[nt][3];
        }
        rs0 += __shfl_xor_sync(0xffffffffu, rs0, 1);
        rs0 += __shfl_xor_sync(0xffffffffu, rs0, 2);
        rs1 += __shfl_xor_sync(0xffffffffu, rs1, 1);
        rs1 += __shfl_xor_sync(0xffffffffu, rs1, 2);
        l0 += rs0; l1 += rs1;

        // ---- build P fragments (pure register repack) ----
        u32 pah[4][4], pal[4][4];
#pragma unroll
        for (int kb = 0; kb < 4; kb++) {
            float* sa = s[2 * kb];
            float* sb = s[2 * kb + 1];
            pah[kb][0] = pk2(sa[0], sa[1]);
            pah[kb][1] = pk2(sa[2], sa[3]);
            pah[kb][2] = pk2(sb[0], sb[1]);
            pah[kb][3] = pk2(sb[2], sb[3]);
            float la0 = sa[0] - __bfloat162float(__float2bfloat16(sa[0]));
            float la1 = sa[1] - __bfloat162float(__float2bfloat16(sa[1]));
            float la2 = sa[2] - __bfloat162float(__float2bfloat16(sa[2]));
            float la3 = sa[3] - __bfloat162float(__float2bfloat16(sa[3]));
            float lb0 = sb[0] - __bfloat162float(__float2bfloat16(sb[0]));
            float lb1 = sb[1] - __bfloat162float(__float2bfloat16(sb[1]));
            float lb2 = sb[2] - __bfloat162float(__float2bfloat16(sb[2]));
            float lb3 = sb[3] - __bfloat162float(__float2bfloat16(sb[3]));
            pal[kb][0] = pk2(la0, la1);
            pal[kb][1] = pk2(la2, la3);
            pal[kb][2] = pk2(lb0, lb1);
            pal[kb][3] = pk2(lb2, lb3);
        }

        // ---- O += P V (3-pass bf16x3) ----
#pragma unroll
        for (int nt = 0; nt < 8; nt++) {
#pragma unroll
            for (int kb = 0; kb < 4; kb++) {
                int off = (nt * 8 + g) * APAD + kb * 16 + t * 2;
                u32 bh2[2], bl2[2];
                bh2[0] = *(const u32*)&Vh[off];
                bh2[1] = *(const u32*)&Vh[off + 8];
                bl2[0] = *(const u32*)&Vl[off];
                bl2[1] = *(const u32*)&Vl[off + 8];
                mma_bf16(o[nt], pah[kb], bh2);
                mma_bf16(o[nt], pah[kb], bl2);
                mma_bf16(o[nt], pal[kb], bh2);
            }
        }
    }

    // ---- normalize + write ctx ----
    float inv0 = 1.0f / l0, inv1 = 1.0f / l1;
    int r0 = qt * 64 + wq * 16 + g;
    size_t ob0 = ((size_t)(b * TSEQ + r0)) * CDIM + hh * HD;
    size_t ob1 = ((size_t)(b * TSEQ + r0 + 8)) * CDIM + hh * HD;
#pragma unroll
    for (int nt = 0; nt < 8; nt++) {
        int c = nt * 8 + t * 2;
        g_ctx[ob0 + c]     = o[nt][0] * inv0;
        g_ctx[ob0 + c + 1] = o[nt][1] * inv0;
        g_ctx[ob1 + c]     = o[nt][2] * inv1;
        g_ctx[ob1 + c + 1] = o[nt][3] * inv1;
    }
}

// ---------------- log-softmax NLL per row --------------------------------
__global__ __launch_bounds__(256)
void loss_kernel(const float* __restrict__ logits, const int* __restrict__ target) {
    __shared__ float sm[256];
    int row = blockIdx.x;
    const float* lr = logits + (size_t)row * VDIM;
    int tid = threadIdx.x;

    float mx = -1e30f;
    for (int i = tid; i < VDIM; i += 256) mx = fmaxf(mx, lr[i]);
    sm[tid] = mx; __syncthreads();
    for (int s = 128; s > 0; s >>= 1) {
        if (tid < s) sm[tid] = fmaxf(sm[tid], sm[tid + s]);
        __syncthreads();
    }
    mx = sm[0]; __syncthreads();

    float se = 0.f;
    for (int i = tid; i < VDIM; i += 256) se += __expf(lr[i] - mx);
    sm[tid] = se; __syncthreads();
    for (int s = 128; s > 0; s >>= 1) {
        if (tid < s) sm[tid] += sm[tid + s];
        __syncthreads();
    }
    if (tid == 0)
        g_nll[row] = logf(sm[0]) + mx - lr[target[row]];
}

__global__ __launch_bounds__(1024)
void reduce_loss_kernel(float* __restrict__ out, long long loss_idx) {
    __shared__ float sm[1024];
    int tid = threadIdx.x;
    float s = 0.f;
    for (int i = tid; i < BT; i += 1024) s += g_nll[i];
    sm[tid] = s; __syncthreads();
    for (int st = 512; st > 0; st >>= 1) {
        if (tid < st) sm[tid] += sm[tid + st];
        __syncthreads();
    }
    if (tid == 0 && loss_idx >= 0)
        out[loss_idx] = sm[0] / (float)BT;
}

// ---------------- launch --------------------------------------------------
extern "C" void kernel_launch(void* const* d_in, const int* in_sizes, int n_in,
                              void* d_out, int out_size) {
    const int*   x      = (const int*)  d_in[0];
    const int*   target = (const int*)  d_in[1];
    const float* embed_w= (const float*)d_in[2];
    const float* pos    = (const float*)d_in[3];
    const float* Wq     = (const float*)d_in[4];
    const float* bq     = (const float*)d_in[5];
    const float* Wk     = (const float*)d_in[6];
    const float* bk     = (const float*)d_in[7];
    const float* Wv     = (const float*)d_in[8];
    const float* bv     = (const float*)d_in[9];
    const float* Wo     = (const float*)d_in[10];
    const float* bo     = (const float*)d_in[11];
    const float* Wu     = (const float*)d_in[12];
    float* out = (float*)d_out;

    float *h, *q, *k, *v, *ctx, *logits_scratch;
    cudaGetSymbolAddress((void**)&h,   g_h);
    cudaGetSymbolAddress((void**)&q,   g_q);
    cudaGetSymbolAddress((void**)&k,   g_k);
    cudaGetSymbolAddress((void**)&v,   g_v);
    cudaGetSymbolAddress((void**)&ctx, g_ctx);
    cudaGetSymbolAddress((void**)&logits_scratch, g_logits);

    __nv_bfloat16 *ahi, *alo, *wqhi, *wqlo, *wkhi, *wklo, *wvhi, *wvlo, *wohi, *wolo, *wuhi, *wulo;
    cudaGetSymbolAddress((void**)&ahi, g_ahi);
    cudaGetSymbolAddress((void**)&alo, g_alo);
    cudaGetSymbolAddress((void**)&wqhi, g_wqhi); cudaGetSymbolAddress((void**)&wqlo, g_wqlo);
    cudaGetSymbolAddress((void**)&wkhi, g_wkhi); cudaGetSymbolAddress((void**)&wklo, g_wklo);
    cudaGetSymbolAddress((void**)&wvhi, g_wvhi); cudaGetSymbolAddress((void**)&wvlo, g_wvlo);
    cudaGetSymbolAddress((void**)&wohi, g_wohi); cudaGetSymbolAddress((void**)&wolo, g_wolo);
    cudaGetSymbolAddress((void**)&wuhi, g_wuhi); cudaGetSymbolAddress((void**)&wulo, g_wulo);

    static bool attr_set = false;
    if (!attr_set) {
        cudaFuncSetAttribute(gemm_bf16x3, cudaFuncAttributeMaxDynamicSharedMemorySize, GSMEM);
        cudaFuncSetAttribute(attn_mma_kernel, cudaFuncAttributeMaxDynamicSharedMemorySize, ASMEM);
        attr_set = true;
    }

    const size_t nlogits = (size_t)BT * VDIM;
    float* logits_dst = ((size_t)out_size >= nlogits) ? out : logits_scratch;
    long long loss_idx;
    if ((size_t)out_size > nlogits)       loss_idx = (long long)nlogits;
    else if ((size_t)out_size < nlogits)  loss_idx = 0;
    else                                  loss_idx = -1;

    // 0) weight splits
    {
        size_t nw = (size_t)LAYERS * CDIM * CDIM;
        unsigned gb = (unsigned)((nw + 255) / 256);
        split_kernel<<<gb, 256>>>(Wq, wqhi, wqlo, nw);
        split_kernel<<<gb, 256>>>(Wk, wkhi, wklo, nw);
        split_kernel<<<gb, 256>>>(Wv, wvhi, wvlo, nw);
        split_kernel<<<gb, 256>>>(Wo, wohi, wolo, nw);
        size_t nu = (size_t)VDIM * CDIM;
        split_kernel<<<(unsigned)((nu + 255) / 256), 256>>>(Wu, wuhi, wulo, nu);
    }

    // 1) embedding + positional
    {
        size_t total = (size_t)BT * CDIM;
        embed_kernel<<<(unsigned)((total + 255) / 256), 256>>>(x, embed_w, pos);
    }

    // 2) transformer layers
    const size_t nh = (size_t)BT * CDIM;
    unsigned gsplit = (unsigned)((nh + 255) / 256);
    dim3 gC(CDIM / 64, BT / 128);
    for (int l = 0; l < LAYERS; l++) {
        size_t woff = (size_t)l * CDIM * CDIM;
        split_kernel<<<gsplit, 256>>>(h, ahi, alo, nh);
        gemm_bf16x3<<<gC, GT, GSMEM>>>(ahi, alo, wqhi + woff, wqlo + woff,
                                       bq + l * CDIM, nullptr, q, BT, CDIM, CDIM);
        gemm_bf16x3<<<gC, GT, GSMEM>>>(ahi, alo, wkhi + woff, wklo + woff,
                                       bk + l * CDIM, nullptr, k, BT, CDIM, CDIM);
        gemm_bf16x3<<<gC, GT, GSMEM>>>(ahi, alo, wvhi + woff, wvlo + woff,
                                       bv + l * CDIM, nullptr, v, BT, CDIM, CDIM);

        attn_mma_kernel<<<dim3(TSEQ / 64, BATCH * NHEAD), 128, ASMEM>>>();

        split_kernel<<<gsplit, 256>>>(ctx, ahi, alo, nh);
        gemm_bf16x3<<<gC, GT, GSMEM>>>(ahi, alo, wohi + woff, wolo + woff,
                                       bo + l * CDIM, h, h, BT, CDIM, CDIM);
    }

    // 3) logits = h @ Wu^T
    split_kernel<<<gsplit, 256>>>(h, ahi, alo, nh);
    gemm_bf16x3<<<dim3(VDIM / 64, BT / 128), GT, GSMEM>>>(ahi, alo, wuhi, wulo,
                                                          nullptr, nullptr,
                                                          logits_dst, BT, VDIM, CDIM);

    // 4) loss
    loss_kernel<<<BT, 256>>>(logits_dst, target);
    reduce_loss_kernel<<<1, 1024>>>(out, loss_idx);
}

// round 10
// speedup vs baseline: 2.9189x; 1.0455x over previous
#include <cuda_runtime.h>
#include <cuda_bf16.h>
#include <stdint.h>
#include <math.h>

typedef unsigned int u32;

// ---------------- problem constants (match setup_inputs) ----------------
#define BATCH  2
#define TSEQ   2048
#define CDIM   1024
#define VDIM   8192
#define LAYERS 2
#define NHEAD  16
#define HD     64            // CDIM / NHEAD
#define BT     (BATCH * TSEQ)   // 4096 rows

// ---------------- scratch (device globals: allocation-free) -------------
__device__ float g_h[BT * CDIM];      // hidden state  [B*T, C]
__device__ float g_q[BT * CDIM];
__device__ float g_k[BT * CDIM];
__device__ float g_v[BT * CDIM];
__device__ float g_ctx[BT * CDIM];
__device__ float g_logits[(size_t)BT * VDIM];  // fallback if d_out can't hold logits
__device__ float g_nll[BT];

// bf16 hi/lo splits
__device__ __nv_bfloat16 g_ahi[BT * CDIM];
__device__ __nv_bfloat16 g_alo[BT * CDIM];
__device__ __nv_bfloat16 g_wqhi[LAYERS * CDIM * CDIM];
__device__ __nv_bfloat16 g_wqlo[LAYERS * CDIM * CDIM];
__device__ __nv_bfloat16 g_wkhi[LAYERS * CDIM * CDIM];
__device__ __nv_bfloat16 g_wklo[LAYERS * CDIM * CDIM];
__device__ __nv_bfloat16 g_wvhi[LAYERS * CDIM * CDIM];
__device__ __nv_bfloat16 g_wvlo[LAYERS * CDIM * CDIM];
__device__ __nv_bfloat16 g_wohi[LAYERS * CDIM * CDIM];
__device__ __nv_bfloat16 g_wolo[LAYERS * CDIM * CDIM];
__device__ __nv_bfloat16 g_wuhi[(size_t)VDIM * CDIM];
__device__ __nv_bfloat16 g_wulo[(size_t)VDIM * CDIM];

// ---------------- fp32 -> bf16 hi/lo split --------------------------------
__global__ void split_kernel(const float* __restrict__ src,
                             __nv_bfloat16* __restrict__ hi,
                             __nv_bfloat16* __restrict__ lo, size_t n) {
    size_t i = (size_t)blockIdx.x * blockDim.x + threadIdx.x;
    if (i >= n) return;
    float x = src[i];
    __nv_bfloat16 h = __float2bfloat16(x);
    hi[i] = h;
    lo[i] = __float2bfloat16(x - __bfloat162float(h));
}

// ---------------- embedding + positional ----------------
__global__ void embed_kernel(const int* __restrict__ x,
                             const float* __restrict__ embed_w,
                             const float* __restrict__ pos) {
    size_t i = (size_t)blockIdx.x * blockDim.x + threadIdx.x;
    size_t total = (size_t)BT * CDIM;
    if (i >= total) return;
    int c  = (int)(i % CDIM);
    size_t bt = i / CDIM;
    int t  = (int)(bt % TSEQ);
    int tok = x[bt];
    g_h[i] = embed_w[(size_t)tok * CDIM + c] + pos[(size_t)t * CDIM + c];
}

// ---------------- shared helpers ------------------------------------------
__device__ __forceinline__ void cp16(u32 s, const void* g) {
    asm volatile("cp.async.cg.shared.global [%0], [%1], 16;\n" :: "r"(s), "l"(g));
}
__device__ __forceinline__ void mma_bf16(float* d, const u32* a, const u32* b) {
    asm volatile(
        "mma.sync.aligned.m16n8k16.row.col.f32.bf16.bf16.f32 "
        "{%0,%1,%2,%3}, {%4,%5,%6,%7}, {%8,%9}, {%0,%1,%2,%3};\n"
        : "+f"(d[0]), "+f"(d[1]), "+f"(d[2]), "+f"(d[3])
        : "r"(a[0]), "r"(a[1]), "r"(a[2]), "r"(a[3]), "r"(b[0]), "r"(b[1]));
}
__device__ __forceinline__ void ldm4(u32* r, u32 a) {
    asm volatile("ldmatrix.sync.aligned.m8n8.x4.shared.b16 {%0,%1,%2,%3}, [%4];"
                 : "=r"(r[0]), "=r"(r[1]), "=r"(r[2]), "=r"(r[3]) : "r"(a));
}
__device__ __forceinline__ u32 pk2(float x, float y) {
    __nv_bfloat162 p = __floats2bfloat162_rn(x, y);
    return *(u32*)&p;
}

// ---------------- bf16x3 tensor-core GEMM (ldmatrix + 128x128 tile) -------
// out[m,n] = sum_k A[m,k]*W[n,k] (+bias[n]) (+res[m,n]); A,W pre-split hi/lo.
// CTA tile 128(M) x 128(N) x 32(K); 8 warps (2x4), warp tile 64x32.
#define GT 256
#define RS      80                       // padded row bytes (32 bf16 + 8 pad)
#define ARRB    (128 * RS)               // 10240 per array
#define STAGE   (4 * ARRB)               // Ah, Al, Bh, Bl = 40960
#define GSMEM   (2 * STAGE)              // 81920

__global__ __launch_bounds__(GT)
void gemm_bf16x3(const __nv_bfloat16* __restrict__ Ahi, const __nv_bfloat16* __restrict__ Alo,
                 const __nv_bfloat16* __restrict__ Whi, const __nv_bfloat16* __restrict__ Wlo,
                 const float* __restrict__ bias, const float* __restrict__ res,
                 float* __restrict__ out, int M, int N, int K) {
    extern __shared__ char smraw[];
    u32 sbase = (u32)__cvta_generic_to_shared(smraw);

    int tid = threadIdx.x;
    int lane = tid & 31, wid = tid >> 5;
    int warp_m = wid & 1;        // 2 -> 64 rows each
    int warp_n = wid >> 1;       // 4 -> 32 cols each
    int m0 = blockIdx.y * 128, n0 = blockIdx.x * 128;
    int g = lane >> 2;           // 0..7
    int t2 = (lane & 3) * 2;     // 0,2,4,6

    float acc[4][4][4];
#pragma unroll
    for (int i = 0; i < 4; i++)
#pragma unroll
        for (int j = 0; j < 4; j++)
#pragma unroll
            for (int r = 0; r < 4; r++) acc[i][j][r] = 0.f;

    int NKB = K >> 5;

    // ---- async load of one 128x32 A + 128x32 B stage (hi+lo) ----
    auto issue_loads = [&](int kb, int s) {
        int kk = kb << 5;
        u32 st = sbase + s * STAGE;
#pragma unroll
        for (int ii = 0; ii < 8; ii++) {
            int i = tid + ii * GT;            // 0..2047
            int arr = i >> 9;                 // 0:Ah 1:Al 2:Bh 3:Bl
            int rem = i & 511;
            int r = rem >> 2, gg = rem & 3;   // row 0..127, 16B chunk 0..3
            const __nv_bfloat16* src = (arr == 0) ? Ahi : (arr == 1) ? Alo
                                      : (arr == 2) ? Whi : Wlo;
            int row = ((arr < 2) ? m0 : n0) + r;
            u32 dst = st + (u32)arr * ARRB + (u32)(r * RS + gg * 16);
            cp16(dst, src + (size_t)row * K + kk + gg * 8);
        }
    };

    issue_loads(0, 0);
    asm volatile("cp.async.commit_group;\n");
    if (NKB > 1) {
        issue_loads(1, 1);
        asm volatile("cp.async.commit_group;\n");
    }

    for (int kb = 0; kb < NKB; kb++) {
        if (kb + 1 < NKB) asm volatile("cp.async.wait_group 1;\n" ::: "memory");
        else              asm volatile("cp.async.wait_group 0;\n" ::: "memory");
        __syncthreads();

        u32 st = sbase + (kb & 1) * STAGE;

#pragma unroll
        for (int ks = 0; ks < 2; ks++) {
            int kby = ks * 32;    // byte offset of this k=16 slice within 64B row

            // A fragments via ldmatrix.x4: rows lane&15, k-half lane>>4
            u32 ah[4][4], al[4][4];
#pragma unroll
            for (int mi = 0; mi < 4; mi++) {
                u32 arow = st + (u32)((warp_m * 64 + mi * 16 + (lane & 15)) * RS
                                      + kby + (lane >> 4) * 16);
                ldm4(ah[mi], arow);
                ldm4(al[mi], arow + ARRB);
            }
            // B fragments via ldmatrix.x4: 4 ni tiles per k-half
            u32 bh[2][4], bl[2][4];
#pragma unroll
            for (int kh = 0; kh < 2; kh++) {
                u32 brow = st + 2 * ARRB + (u32)((warp_n * 32 + lane) * RS
                                                 + kby + kh * 16);
                ldm4(bh[kh], brow);
                ldm4(bl[kh], brow + ARRB);
            }
#pragma unroll
            for (int mi = 0; mi < 4; mi++)
#pragma unroll
                for (int ni = 0; ni < 4; ni++) {
                    u32 bfh[2] = {bh[0][ni], bh[1][ni]};
                    u32 bfl[2] = {bl[0][ni], bl[1][ni]};
                    mma_bf16(acc[mi][ni], ah[mi], bfh);
                    mma_bf16(acc[mi][ni], ah[mi], bfl);
                    mma_bf16(acc[mi][ni], al[mi], bfh);
                }
        }
        __syncthreads();

        if (kb + 2 < NKB) {
            issue_loads(kb + 2, kb & 1);
            asm volatile("cp.async.commit_group;\n");
        }
    }

    // ---- epilogue ----
#pragma unroll
    for (int mi = 0; mi < 4; mi++) {
        int r0 = m0 + warp_m * 64 + mi * 16 + g;
#pragma unroll
        for (int ni = 0; ni < 4; ni++) {
            int c = n0 + warp_n * 32 + ni * 8 + t2;
            float v0 = acc[mi][ni][0], v1 = acc[mi][ni][1];
            float v2 = acc[mi][ni][2], v3 = acc[mi][ni][3];
            if (bias) { float b0 = bias[c], b1 = bias[c + 1]; v0 += b0; v1 += b1; v2 += b0; v3 += b1; }
            if (res) {
                v0 += res[(size_t)r0 * N + c];       v1 += res[(size_t)r0 * N + c + 1];
                v2 += res[(size_t)(r0 + 8) * N + c]; v3 += res[(size_t)(r0 + 8) * N + c + 1];
            }
            out[(size_t)r0 * N + c] = v0;       out[(size_t)r0 * N + c + 1] = v1;
            out[(size_t)(r0 + 8) * N + c] = v2; out[(size_t)(r0 + 8) * N + c + 1] = v3;
        }
    }
}

// ---------------- MMA flash attention (unchanged, proven) -----------------
#define APAD 72
#define ATSZ (64 * APAD)
#define ASMEM (6 * ATSZ * 2)

__global__ __launch_bounds__(128)
void attn_mma_kernel() {
    extern __shared__ __nv_bfloat16 asmem[];
    __nv_bfloat16* Qh = asmem;
    __nv_bfloat16* Ql = Qh + ATSZ;
    __nv_bfloat16* Kh = Ql + ATSZ;
    __nv_bfloat16* Kl = Kh + ATSZ;
    __nv_bfloat16* Vh = Kl + ATSZ;   // transposed: Vh[d][key]
    __nv_bfloat16* Vl = Vh + ATSZ;

    int tid = threadIdx.x, lane = tid & 31, wq = tid >> 5;
    int g = lane >> 2, t = lane & 3;
    int bh = blockIdx.y, b = bh >> 4, hh = bh & 15;
    int qt = blockIdx.x;

    size_t qbase = ((size_t)(b * TSEQ + qt * 64)) * CDIM + hh * HD;

    for (int i = tid; i < 64 * 16; i += 128) {
        int r = i >> 4, c4 = (i & 15) << 2;
        float4 qv = *(const float4*)&g_q[qbase + (size_t)r * CDIM + c4];
        float xs[4] = {qv.x * 0.125f, qv.y * 0.125f, qv.z * 0.125f, qv.w * 0.125f};
#pragma unroll
        for (int j = 0; j < 4; j++) {
            __nv_bfloat16 hb = __float2bfloat16(xs[j]);
            Qh[r * APAD + c4 + j] = hb;
            Ql[r * APAD + c4 + j] = __float2bfloat16(xs[j] - __bfloat162float(hb));
        }
    }
    __syncthreads();

    u32 qah[4][4], qal[4][4];
#pragma unroll
    for (int kb = 0; kb < 4; kb++) {
        int r = wq * 16 + g, kk = kb * 16 + t * 2;
        qah[kb][0] = *(const u32*)&Qh[r * APAD + kk];
        qah[kb][1] = *(const u32*)&Qh[(r + 8) * APAD + kk];
        qah[kb][2] = *(const u32*)&Qh[r * APAD + kk + 8];
        qah[kb][3] = *(const u32*)&Qh[(r + 8) * APAD + kk + 8];
        qal[kb][0] = *(const u32*)&Ql[r * APAD + kk];
        qal[kb][1] = *(const u32*)&Ql[(r + 8) * APAD + kk];
        qal[kb][2] = *(const u32*)&Ql[r * APAD + kk + 8];
        qal[kb][3] = *(const u32*)&Ql[(r + 8) * APAD + kk + 8];
    }

    float m0r = -1e30f, m1r = -1e30f, l0 = 0.f, l1 = 0.f;
    float o[8][4];
#pragma unroll
    for (int nt = 0; nt < 8; nt++)
#pragma unroll
        for (int i = 0; i < 4; i++) o[nt][i] = 0.f;

    for (int kt = 0; kt <= qt; kt++) {
        __syncthreads();
        size_t kbase = ((size_t)(b * TSEQ + kt * 64)) * CDIM + hh * HD;
        for (int i = tid; i < 64 * 16; i += 128) {
            int r = i >> 4, c4 = (i & 15) << 2;
            size_t gb = kbase + (size_t)r * CDIM + c4;
            float4 kv = *(const float4*)&g_k[gb];
            float ks[4] = {kv.x, kv.y, kv.z, kv.w};
#pragma unroll
            for (int j = 0; j < 4; j++) {
                __nv_bfloat16 hb = __float2bfloat16(ks[j]);
                Kh[r * APAD + c4 + j] = hb;
                Kl[r * APAD + c4 + j] = __float2bfloat16(ks[j] - __bfloat162float(hb));
            }
            float4 vv = *(const float4*)&g_v[gb];
            float vs[4] = {vv.x, vv.y, vv.z, vv.w};
#pragma unroll
            for (int j = 0; j < 4; j++) {
                __nv_bfloat16 hb = __float2bfloat16(vs[j]);
                Vh[(c4 + j) * APAD + r] = hb;
                Vl[(c4 + j) * APAD + r] = __float2bfloat16(vs[j] - __bfloat162float(hb));
            }
        }
        __syncthreads();

        float s[8][4];
#pragma unroll
        for (int nt = 0; nt < 8; nt++)
#pragma unroll
            for (int i = 0; i < 4; i++) s[nt][i] = 0.f;

#pragma unroll
        for (int nt = 0; nt < 8; nt++) {
#pragma unroll
            for (int kb = 0; kb < 4; kb++) {
                int off = (nt * 8 + g) * APAD + kb * 16 + t * 2;
                u32 bh2[2], bl2[2];
                bh2[0] = *(const u32*)&Kh[off];
                bh2[1] = *(const u32*)&Kh[off + 8];
                bl2[0] = *(const u32*)&Kl[off];
                bl2[1] = *(const u32*)&Kl[off + 8];
                mma_bf16(s[nt], qah[kb], bh2);
                mma_bf16(s[nt], qah[kb], bl2);
                mma_bf16(s[nt], qal[kb], bh2);
            }
        }

        if (kt == qt) {
            int r0 = wq * 16 + g, r1 = r0 + 8;
#pragma unroll
            for (int nt = 0; nt < 8; nt++) {
                int c0 = nt * 8 + t * 2;
                if (c0 > r0)     s[nt][0] = -1e30f;
                if (c0 + 1 > r0) s[nt][1] = -1e30f;
                if (c0 > r1)     s[nt][2] = -1e30f;
                if (c0 + 1 > r1) s[nt][3] = -1e30f;
            }
        }

        float tm0 = -1e30f, tm1 = -1e30f;
#pragma unroll
        for (int nt = 0; nt < 8; nt++) {
            tm0 = fmaxf(tm0, fmaxf(s[nt][0], s[nt][1]));
            tm1 = fmaxf(tm1, fmaxf(s[nt][2], s[nt][3]));
        }
        tm0 = fmaxf(tm0, __shfl_xor_sync(0xffffffffu, tm0, 1));
        tm0 = fmaxf(tm0, __shfl_xor_sync(0xffffffffu, tm0, 2));
        tm1 = fmaxf(tm1, __shfl_xor_sync(0xffffffffu, tm1, 1));
        tm1 = fmaxf(tm1, __shfl_xor_sync(0xffffffffu, tm1, 2));

        float mn0 = fmaxf(m0r, tm0), mn1 = fmaxf(m1r, tm1);
        float cf0 = __expf(m0r - mn0), cf1 = __expf(m1r - mn1);
        l0 *= cf0; l1 *= cf1;
#pragma unroll
        for (int nt = 0; nt < 8; nt++) {
            o[nt][0] *= cf0; o[nt][1] *= cf0;
            o[nt][2] *= cf1; o[nt][3] *= cf1;
        }
        m0r = mn0; m1r = mn1;

        float rs0 = 0.f, rs1 = 0.f;
#pragma unroll
        for (int nt = 0; nt < 8; nt++) {
            s[nt][0] = __expf(s[nt][0] - mn0);
            s[nt][1] = __expf(s[nt][1] - mn0);
            s[nt][2] = __expf(s[nt][2] - mn1);
            s[nt][3] = __expf(s[nt][3] - mn1);
            rs0 += s[nt][0] + s[nt][1];
            rs1 += s[nt][2] + s[nt][3];
        }
        rs0 += __shfl_xor_sync(0xffffffffu, rs0, 1);
        rs0 += __shfl_xor_sync(0xffffffffu, rs0, 2);
        rs1 += __shfl_xor_sync(0xffffffffu, rs1, 1);
        rs1 += __shfl_xor_sync(0xffffffffu, rs1, 2);
        l0 += rs0; l1 += rs1;

        u32 pah[4][4], pal[4][4];
#pragma unroll
        for (int kb = 0; kb < 4; kb++) {
            float* sa = s[2 * kb];
            float* sb2 = s[2 * kb + 1];
            pah[kb][0] = pk2(sa[0], sa[1]);
            pah[kb][1] = pk2(sa[2], sa[3]);
            pah[kb][2] = pk2(sb2[0], sb2[1]);
            pah[kb][3] = pk2(sb2[2], sb2[3]);
            float la0 = sa[0] - __bfloat162float(__float2bfloat16(sa[0]));
            float la1 = sa[1] - __bfloat162float(__float2bfloat16(sa[1]));
            float la2 = sa[2] - __bfloat162float(__float2bfloat16(sa[2]));
            float la3 = sa[3] - __bfloat162float(__float2bfloat16(sa[3]));
            float lb0 = sb2[0] - __bfloat162float(__float2bfloat16(sb2[0]));
            float lb1 = sb2[1] - __bfloat162float(__float2bfloat16(sb2[1]));
            float lb2 = sb2[2] - __bfloat162float(__float2bfloat16(sb2[2]));
            float lb3 = sb2[3] - __bfloat162float(__float2bfloat16(sb2[3]));
            pal[kb][0] = pk2(la0, la1);
            pal[kb][1] = pk2(la2, la3);
            pal[kb][2] = pk2(lb0, lb1);
            pal[kb][3] = pk2(lb2, lb3);
        }

#pragma unroll
        for (int nt = 0; nt < 8; nt++) {
#pragma unroll
            for (int kb = 0; kb < 4; kb++) {
                int off = (nt * 8 + g) * APAD + kb * 16 + t * 2;
                u32 bh2[2], bl2[2];
                bh2[0] = *(const u32*)&Vh[off];
                bh2[1] = *(const u32*)&Vh[off + 8];
                bl2[0] = *(const u32*)&Vl[off];
                bl2[1] = *(const u32*)&Vl[off + 8];
                mma_bf16(o[nt], pah[kb], bh2);
                mma_bf16(o[nt], pah[kb], bl2);
                mma_bf16(o[nt], pal[kb], bh2);
            }
        }
    }

    float inv0 = 1.0f / l0, inv1 = 1.0f / l1;
    int r0 = qt * 64 + wq * 16 + g;
    size_t ob0 = ((size_t)(b * TSEQ + r0)) * CDIM + hh * HD;
    size_t ob1 = ((size_t)(b * TSEQ + r0 + 8)) * CDIM + hh * HD;
#pragma unroll
    for (int nt = 0; nt < 8; nt++) {
        int c = nt * 8 + t * 2;
        g_ctx[ob0 + c]     = o[nt][0] * inv0;
        g_ctx[ob0 + c + 1] = o[nt][1] * inv0;
        g_ctx[ob1 + c]     = o[nt][2] * inv1;
        g_ctx[ob1 + c + 1] = o[nt][3] * inv1;
    }
}

// ---------------- log-softmax NLL per row --------------------------------
__global__ __launch_bounds__(256)
void loss_kernel(const float* __restrict__ logits, const int* __restrict__ target) {
    __shared__ float sm[256];
    int row = blockIdx.x;
    const float* lr = logits + (size_t)row * VDIM;
    int tid = threadIdx.x;

    float mx = -1e30f;
    for (int i = tid; i < VDIM; i += 256) mx = fmaxf(mx, lr[i]);
    sm[tid] = mx; __syncthreads();
    for (int s = 128; s > 0; s >>= 1) {
        if (tid < s) sm[tid] = fmaxf(sm[tid], sm[tid + s]);
        __syncthreads();
    }
    mx = sm[0]; __syncthreads();

    float se = 0.f;
    for (int i = tid; i < VDIM; i += 256) se += __expf(lr[i] - mx);
    sm[tid] = se; __syncthreads();
    for (int s = 128; s > 0; s >>= 1) {
        if (tid < s) sm[tid] += sm[tid + s];
        __syncthreads();
    }
    if (tid == 0)
        g_nll[row] = logf(sm[0]) + mx - lr[target[row]];
}

__global__ __launch_bounds__(1024)
void reduce_loss_kernel(float* __restrict__ out, long long loss_idx) {
    __shared__ float sm[1024];
    int tid = threadIdx.x;
    float s = 0.f;
    for (int i = tid; i < BT; i += 1024) s += g_nll[i];
    sm[tid] = s; __syncthreads();
    for (int st = 512; st > 0; st >>= 1) {
        if (tid < st) sm[tid] += sm[tid + st];
        __syncthreads();
    }
    if (tid == 0 && loss_idx >= 0)
        out[loss_idx] = sm[0] / (float)BT;
}

// ---------------- launch --------------------------------------------------
extern "C" void kernel_launch(void* const* d_in, const int* in_sizes, int n_in,
                              void* d_out, int out_size) {
    const int*   x      = (const int*)  d_in[0];
    const int*   target = (const int*)  d_in[1];
    const float* embed_w= (const float*)d_in[2];
    const float* pos    = (const float*)d_in[3];
    const float* Wq     = (const float*)d_in[4];
    const float* bq     = (const float*)d_in[5];
    const float* Wk     = (const float*)d_in[6];
    const float* bk     = (const float*)d_in[7];
    const float* Wv     = (const float*)d_in[8];
    const float* bv     = (const float*)d_in[9];
    const float* Wo     = (const float*)d_in[10];
    const float* bo     = (const float*)d_in[11];
    const float* Wu     = (const float*)d_in[12];
    float* out = (float*)d_out;

    float *h, *q, *k, *v, *ctx, *logits_scratch;
    cudaGetSymbolAddress((void**)&h,   g_h);
    cudaGetSymbolAddress((void**)&q,   g_q);
    cudaGetSymbolAddress((void**)&k,   g_k);
    cudaGetSymbolAddress((void**)&v,   g_v);
    cudaGetSymbolAddress((void**)&ctx, g_ctx);
    cudaGetSymbolAddress((void**)&logits_scratch, g_logits);

    __nv_bfloat16 *ahi, *alo, *wqhi, *wqlo, *wkhi, *wklo, *wvhi, *wvlo, *wohi, *wolo, *wuhi, *wulo;
    cudaGetSymbolAddress((void**)&ahi, g_ahi);
    cudaGetSymbolAddress((void**)&alo, g_alo);
    cudaGetSymbolAddress((void**)&wqhi, g_wqhi); cudaGetSymbolAddress((void**)&wqlo, g_wqlo);
    cudaGetSymbolAddress((void**)&wkhi, g_wkhi); cudaGetSymbolAddress((void**)&wklo, g_wklo);
    cudaGetSymbolAddress((void**)&wvhi, g_wvhi); cudaGetSymbolAddress((void**)&wvlo, g_wvlo);
    cudaGetSymbolAddress((void**)&wohi, g_wohi); cudaGetSymbolAddress((void**)&wolo, g_wolo);
    cudaGetSymbolAddress((void**)&wuhi, g_wuhi); cudaGetSymbolAddress((void**)&wulo, g_wulo);

    static bool attr_set = false;
    if (!attr_set) {
        cudaFuncSetAttribute(gemm_bf16x3, cudaFuncAttributeMaxDynamicSharedMemorySize, GSMEM);
        cudaFuncSetAttribute(attn_mma_kernel, cudaFuncAttributeMaxDynamicSharedMemorySize, ASMEM);
        attr_set = true;
    }

    const size_t nlogits = (size_t)BT * VDIM;
    float* logits_dst = ((size_t)out_size >= nlogits) ? out : logits_scratch;
    long long loss_idx;
    if ((size_t)out_size > nlogits)       loss_idx = (long long)nlogits;
    else if ((size_t)out_size < nlogits)  loss_idx = 0;
    else                                  loss_idx = -1;

    // 0) weight splits
    {
        size_t nw = (size_t)LAYERS * CDIM * CDIM;
        unsigned gb = (unsigned)((nw + 255) / 256);
        split_kernel<<<gb, 256>>>(Wq, wqhi, wqlo, nw);
        split_kernel<<<gb, 256>>>(Wk, wkhi, wklo, nw);
        split_kernel<<<gb, 256>>>(Wv, wvhi, wvlo, nw);
        split_kernel<<<gb, 256>>>(Wo, wohi, wolo, nw);
        size_t nu = (size_t)VDIM * CDIM;
        split_kernel<<<(unsigned)((nu + 255) / 256), 256>>>(Wu, wuhi, wulo, nu);
    }

    // 1) embedding + positional
    {
        size_t total = (size_t)BT * CDIM;
        embed_kernel<<<(unsigned)((total + 255) / 256), 256>>>(x, embed_w, pos);
    }

    // 2) transformer layers
    const size_t nh = (size_t)BT * CDIM;
    unsigned gsplit = (unsigned)((nh + 255) / 256);
    dim3 gC(CDIM / 128, BT / 128);       // (8, 32)
    for (int l = 0; l < LAYERS; l++) {
        size_t woff = (size_t)l * CDIM * CDIM;
        split_kernel<<<gsplit, 256>>>(h, ahi, alo, nh);
        gemm_bf16x3<<<gC, GT, GSMEM>>>(ahi, alo, wqhi + woff, wqlo + woff,
                                       bq + l * CDIM, nullptr, q, BT, CDIM, CDIM);
        gemm_bf16x3<<<gC, GT, GSMEM>>>(ahi, alo, wkhi + woff, wklo + woff,
                                       bk + l * CDIM, nullptr, k, BT, CDIM, CDIM);
        gemm_bf16x3<<<gC, GT, GSMEM>>>(ahi, alo, wvhi + woff, wvlo + woff,
                                       bv + l * CDIM, nullptr, v, BT, CDIM, CDIM);

        attn_mma_kernel<<<dim3(TSEQ / 64, BATCH * NHEAD), 128, ASMEM>>>();

        split_kernel<<<gsplit, 256>>>(ctx, ahi, alo, nh);
        gemm_bf16x3<<<gC, GT, GSMEM>>>(ahi, alo, wohi + woff, wolo + woff,
                                       bo + l * CDIM, h, h, BT, CDIM, CDIM);
    }

    // 3) logits = h @ Wu^T
    split_kernel<<<gsplit, 256>>>(h, ahi, alo, nh);
    gemm_bf16x3<<<dim3(VDIM / 128, BT / 128), GT, GSMEM>>>(ahi, alo, wuhi, wulo,
                                                           nullptr, nullptr,
                                                           logits_dst, BT, VDIM, CDIM);

    // 4) loss
    loss_kernel<<<BT, 256>>>(logits_dst, target);
    reduce_loss_kernel<<<1, 1024>>>(out, loss_idx);
}

// round 11
// speedup vs baseline: 3.3302x; 1.1409x over previous
#include <cuda_runtime.h>
#include <cuda_bf16.h>
#include <stdint.h>
#include <math.h>

typedef unsigned int u32;

// ---------------- problem constants (match setup_inputs) ----------------
#define BATCH  2
#define TSEQ   2048
#define CDIM   1024
#define VDIM   8192
#define LAYERS 2
#define NHEAD  16
#define HD     64            // CDIM / NHEAD
#define BT     (BATCH * TSEQ)   // 4096 rows

// ---------------- scratch (device globals: allocation-free) -------------
__device__ float g_h[BT * CDIM];      // hidden state  [B*T, C]
__device__ float g_logits[(size_t)BT * VDIM];
__device__ float g_nll[BT];

// bf16 hi/lo activations
__device__ __nv_bfloat16 g_ahi[BT * CDIM];   // current hidden (GEMM A input)
__device__ __nv_bfloat16 g_alo[BT * CDIM];
__device__ __nv_bfloat16 g_qhi[BT * CDIM];
__device__ __nv_bfloat16 g_qlo[BT * CDIM];
__device__ __nv_bfloat16 g_khi[BT * CDIM];
__device__ __nv_bfloat16 g_klo[BT * CDIM];
__device__ __nv_bfloat16 g_vthi[BT * CDIM];  // transposed: [(b,c)][token]
__device__ __nv_bfloat16 g_vtlo[BT * CDIM];
__device__ __nv_bfloat16 g_chi[BT * CDIM];   // ctx hi/lo
__device__ __nv_bfloat16 g_clo[BT * CDIM];

// bf16 hi/lo weights
__device__ __nv_bfloat16 g_wqhi[LAYERS * CDIM * CDIM];
__device__ __nv_bfloat16 g_wqlo[LAYERS * CDIM * CDIM];
__device__ __nv_bfloat16 g_wkhi[LAYERS * CDIM * CDIM];
__device__ __nv_bfloat16 g_wklo[LAYERS * CDIM * CDIM];
__device__ __nv_bfloat16 g_wvhi[LAYERS * CDIM * CDIM];
__device__ __nv_bfloat16 g_wvlo[LAYERS * CDIM * CDIM];
__device__ __nv_bfloat16 g_wohi[LAYERS * CDIM * CDIM];
__device__ __nv_bfloat16 g_wolo[LAYERS * CDIM * CDIM];
__device__ __nv_bfloat16 g_wuhi[(size_t)VDIM * CDIM];
__device__ __nv_bfloat16 g_wulo[(size_t)VDIM * CDIM];

// ---------------- fp32 -> bf16 hi/lo split (weights only now) -------------
__global__ void split_kernel(const float* __restrict__ src,
                             __nv_bfloat16* __restrict__ hi,
                             __nv_bfloat16* __restrict__ lo, size_t n) {
    size_t i = (size_t)blockIdx.x * blockDim.x + threadIdx.x;
    if (i >= n) return;
    float x = src[i];
    __nv_bfloat16 h = __float2bfloat16(x);
    hi[i] = h;
    lo[i] = __float2bfloat16(x - __bfloat162float(h));
}

// ---------------- embedding + positional (+ hi/lo) ------------------------
__global__ void embed_kernel(const int* __restrict__ x,
                             const float* __restrict__ embed_w,
                             const float* __restrict__ pos) {
    size_t i = (size_t)blockIdx.x * blockDim.x + threadIdx.x;
    size_t total = (size_t)BT * CDIM;
    if (i >= total) return;
    int c  = (int)(i % CDIM);
    size_t bt = i / CDIM;
    int t  = (int)(bt % TSEQ);
    int tok = x[bt];
    float val = embed_w[(size_t)tok * CDIM + c] + pos[(size_t)t * CDIM + c];
    g_h[i] = val;
    __nv_bfloat16 hb = __float2bfloat16(val);
    g_ahi[i] = hb;
    g_alo[i] = __float2bfloat16(val - __bfloat162float(hb));
}

// ---------------- shared helpers ------------------------------------------
__device__ __forceinline__ void cp16(u32 s, const void* g) {
    asm volatile("cp.async.cg.shared.global [%0], [%1], 16;\n" :: "r"(s), "l"(g));
}
__device__ __forceinline__ void mma_bf16(float* d, const u32* a, const u32* b) {
    asm volatile(
        "mma.sync.aligned.m16n8k16.row.col.f32.bf16.bf16.f32 "
        "{%0,%1,%2,%3}, {%4,%5,%6,%7}, {%8,%9}, {%0,%1,%2,%3};\n"
        : "+f"(d[0]), "+f"(d[1]), "+f"(d[2]), "+f"(d[3])
        : "r"(a[0]), "r"(a[1]), "r"(a[2]), "r"(a[3]), "r"(b[0]), "r"(b[1]));
}
__device__ __forceinline__ void ldm4(u32* r, u32 a) {
    asm volatile("ldmatrix.sync.aligned.m8n8.x4.shared.b16 {%0,%1,%2,%3}, [%4];"
                 : "=r"(r[0]), "=r"(r[1]), "=r"(r[2]), "=r"(r[3]) : "r"(a));
}
__device__ __forceinline__ u32 pk2(float x, float y) {
    __nv_bfloat162 p = __floats2bfloat162_rn(x, y);
    return *(u32*)&p;
}

// ---------------- bf16x3 tensor-core GEMM (ldmatrix, 128x128 tile) --------
// out[m,n] = sum_k A[m,k]*W[n,k] (+bias) (+res).
// Writes fp32 out (if non-null) and/or bf16 hi/lo split (if non-null),
// optionally in per-batch transposed layout (vtrans: [(b,c)][t]).
#define GT 256
#define RS      80                       // padded row bytes (32 bf16 + 8 pad)
#define ARRB    (128 * RS)               // 10240 per array
#define STAGE   (4 * ARRB)               // 40960
#define GSMEM   (2 * STAGE)              // 81920

__global__ __launch_bounds__(GT)
void gemm_bf16x3(const __nv_bfloat16* __restrict__ Ahi, const __nv_bfloat16* __restrict__ Alo,
                 const __nv_bfloat16* __restrict__ Whi, const __nv_bfloat16* __restrict__ Wlo,
                 const float* __restrict__ bias, const float* __restrict__ res,
                 float* __restrict__ outf,
                 __nv_bfloat16* __restrict__ ohi, __nv_bfloat16* __restrict__ olo,
                 int vtrans, int M, int N, int K) {
    extern __shared__ char smraw[];
    u32 sbase = (u32)__cvta_generic_to_shared(smraw);

    int tid = threadIdx.x;
    int lane = tid & 31, wid = tid >> 5;
    int warp_m = wid & 1;
    int warp_n = wid >> 1;
    int m0 = blockIdx.y * 128, n0 = blockIdx.x * 128;
    int g = lane >> 2;
    int t2 = (lane & 3) * 2;

    float acc[4][4][4];
#pragma unroll
    for (int i = 0; i < 4; i++)
#pragma unroll
        for (int j = 0; j < 4; j++)
#pragma unroll
            for (int r = 0; r < 4; r++) acc[i][j][r] = 0.f;

    int NKB = K >> 5;

    auto issue_loads = [&](int kb, int s) {
        int kk = kb << 5;
        u32 st = sbase + s * STAGE;
#pragma unroll
        for (int ii = 0; ii < 8; ii++) {
            int i = tid + ii * GT;
            int arr = i >> 9;
            int rem = i & 511;
            int r = rem >> 2, gg = rem & 3;
            const __nv_bfloat16* src = (arr == 0) ? Ahi : (arr == 1) ? Alo
                                      : (arr == 2) ? Whi : Wlo;
            int row = ((arr < 2) ? m0 : n0) + r;
            u32 dst = st + (u32)arr * ARRB + (u32)(r * RS + gg * 16);
            cp16(dst, src + (size_t)row * K + kk + gg * 8);
        }
    };

    issue_loads(0, 0);
    asm volatile("cp.async.commit_group;\n");
    if (NKB > 1) {
        issue_loads(1, 1);
        asm volatile("cp.async.commit_group;\n");
    }

    for (int kb = 0; kb < NKB; kb++) {
        if (kb + 1 < NKB) asm volatile("cp.async.wait_group 1;\n" ::: "memory");
        else              asm volatile("cp.async.wait_group 0;\n" ::: "memory");
        __syncthreads();

        u32 st = sbase + (kb & 1) * STAGE;

#pragma unroll
        for (int ks = 0; ks < 2; ks++) {
            int kby = ks * 32;

            u32 ah[4][4], al[4][4];
#pragma unroll
            for (int mi = 0; mi < 4; mi++) {
                u32 arow = st + (u32)((warp_m * 64 + mi * 16 + (lane & 15)) * RS
                                      + kby + (lane >> 4) * 16);
                ldm4(ah[mi], arow);
                ldm4(al[mi], arow + ARRB);
            }
            u32 bh[2][4], bl[2][4];
#pragma unroll
            for (int kh = 0; kh < 2; kh++) {
                u32 brow = st + 2 * ARRB + (u32)((warp_n * 32 + lane) * RS
                                                 + kby + kh * 16);
                ldm4(bh[kh], brow);
                ldm4(bl[kh], brow + ARRB);
            }
#pragma unroll
            for (int mi = 0; mi < 4; mi++)
#pragma unroll
                for (int ni = 0; ni < 4; ni++) {
                    u32 bfh[2] = {bh[0][ni], bh[1][ni]};
                    u32 bfl[2] = {bl[0][ni], bl[1][ni]};
                    mma_bf16(acc[mi][ni], ah[mi], bfh);
                    mma_bf16(acc[mi][ni], ah[mi], bfl);
                    mma_bf16(acc[mi][ni], al[mi], bfh);
                }
        }
        __syncthreads();

        if (kb + 2 < NKB) {
            issue_loads(kb + 2, kb & 1);
            asm volatile("cp.async.commit_group;\n");
        }
    }

    // ---- epilogue ----
    auto emit = [&](int m, int cc, float val) {
        if (outf) outf[(size_t)m * N + cc] = val;
        if (ohi) {
            __nv_bfloat16 hb = __float2bfloat16(val);
            __nv_bfloat16 lb = __float2bfloat16(val - __bfloat162float(hb));
            size_t idx = vtrans
                ? ((size_t)((m >> 11) * N + cc)) * TSEQ + (m & 2047)
                : (size_t)m * N + cc;
            ohi[idx] = hb;
            olo[idx] = lb;
        }
    };
#pragma unroll
    for (int mi = 0; mi < 4; mi++) {
        int r0 = m0 + warp_m * 64 + mi * 16 + g;
#pragma unroll
        for (int ni = 0; ni < 4; ni++) {
            int c = n0 + warp_n * 32 + ni * 8 + t2;
            float v0 = acc[mi][ni][0], v1 = acc[mi][ni][1];
            float v2 = acc[mi][ni][2], v3 = acc[mi][ni][3];
            if (bias) { float b0 = bias[c], b1 = bias[c + 1]; v0 += b0; v1 += b1; v2 += b0; v3 += b1; }
            if (res) {
                v0 += res[(size_t)r0 * N + c];       v1 += res[(size_t)r0 * N + c + 1];
                v2 += res[(size_t)(r0 + 8) * N + c]; v3 += res[(size_t)(r0 + 8) * N + c + 1];
            }
            emit(r0, c, v0);     emit(r0, c + 1, v1);
            emit(r0 + 8, c, v2); emit(r0 + 8, c + 1, v3);
        }
    }
}

// ---------------- MMA flash attention (pre-split KV, cp.async pipeline) ---
// CTA: 128 queries (8 warps x 16); KV tiles of 64 keys, double-buffered.
#define APAD 72
#define QSZB (128 * APAD * 2)        // 18432 bytes per Q array
#define KSZB (64 * APAD * 2)         // 9216 bytes per KV array
#define STGB (4 * KSZB)              // 36864 per stage
#define ASMEM (2 * QSZB + 2 * STGB)  // 110592

__global__ __launch_bounds__(256)
void attn_mma_kernel() {
    extern __shared__ char araw[];
    u32 sb = (u32)__cvta_generic_to_shared(araw);
    __nv_bfloat16* Qh = (__nv_bfloat16*)araw;
    __nv_bfloat16* Ql = Qh + 128 * APAD;

    int tid = threadIdx.x, lane = tid & 31, wq = tid >> 5;
    int g = lane >> 2, t = lane & 3;
    int b = blockIdx.y >> 4, hh = blockIdx.y & 15;
    int qt = (int)(gridDim.x - 1 - blockIdx.x);   // longest CTAs first
    int nkv = 2 * qt + 2;

    // ---- Q tile loads (hi/lo bf16, pre-split) ----
    {
        size_t qb = ((size_t)(b * TSEQ + qt * 128)) * CDIM + hh * HD;
#pragma unroll
        for (int ii = 0; ii < 8; ii++) {
            int i = tid + ii * 256;
            int arr = i >> 10, rem = i & 1023;
            int r = rem >> 3, gg = rem & 7;
            const __nv_bfloat16* src = (arr ? g_qlo : g_qhi) + qb + (size_t)r * CDIM + gg * 8;
            cp16(sb + (u32)arr * QSZB + (u32)(r * (APAD * 2) + gg * 16), src);
        }
    }
    auto load_kv = [&](int kt, int st) {
        u32 base = sb + 2 * QSZB + (u32)st * STGB;
        size_t kb = ((size_t)(b * TSEQ + kt * 64)) * CDIM + hh * HD;
        size_t vb = ((size_t)(b * CDIM + hh * HD)) * TSEQ + kt * 64;
#pragma unroll
        for (int ii = 0; ii < 8; ii++) {
            int i = tid + ii * 256;
            int arr = i >> 9, rem = i & 511;
            int r = rem >> 3, gg = rem & 7;
            const __nv_bfloat16* src;
            if (arr == 0)      src = g_khi  + kb + (size_t)r * CDIM + gg * 8;
            else if (arr == 1) src = g_klo  + kb + (size_t)r * CDIM + gg * 8;
            else if (arr == 2) src = g_vthi + vb + (size_t)r * TSEQ + gg * 8;
            else               src = g_vtlo + vb + (size_t)r * TSEQ + gg * 8;
            cp16(base + (u32)arr * KSZB + (u32)(r * (APAD * 2) + gg * 16), src);
        }
    };
    load_kv(0, 0);
    asm volatile("cp.async.commit_group;\n");   // group: Q + KV0
    load_kv(1, 1);
    asm volatile("cp.async.commit_group;\n");   // group: KV1  (nkv >= 2 always)

    u32 qah[4][4], qal[4][4];
    float m0r = -1e30f, m1r = -1e30f, l0 = 0.f, l1 = 0.f;
    float o[8][4];
#pragma unroll
    for (int nt = 0; nt < 8; nt++)
#pragma unroll
        for (int i = 0; i < 4; i++) o[nt][i] = 0.f;

    for (int kt = 0; kt < nkv; kt++) {
        if (kt + 1 < nkv) asm volatile("cp.async.wait_group 1;\n" ::: "memory");
        else              asm volatile("cp.async.wait_group 0;\n" ::: "memory");
        __syncthreads();

        if (kt == 0) {
            // build Q fragments once (Q arrived with group 0)
#pragma unroll
            for (int kb2 = 0; kb2 < 4; kb2++) {
                int r = wq * 16 + g, kk = kb2 * 16 + t * 2;
                qah[kb2][0] = *(const u32*)&Qh[r * APAD + kk];
                qah[kb2][1] = *(const u32*)&Qh[(r + 8) * APAD + kk];
                qah[kb2][2] = *(const u32*)&Qh[r * APAD + kk + 8];
                qah[kb2][3] = *(const u32*)&Qh[(r + 8) * APAD + kk + 8];
                qal[kb2][0] = *(const u32*)&Ql[r * APAD + kk];
                qal[kb2][1] = *(const u32*)&Ql[(r + 8) * APAD + kk];
                qal[kb2][2] = *(const u32*)&Ql[r * APAD + kk + 8];
                qal[kb2][3] = *(const u32*)&Ql[(r + 8) * APAD + kk + 8];
            }
        }

        __nv_bfloat16* Kh = (__nv_bfloat16*)(araw + 2 * QSZB + (kt & 1) * STGB);
        __nv_bfloat16* Kl = Kh + 64 * APAD;
        __nv_bfloat16* Vh = Kl + 64 * APAD;
        __nv_bfloat16* Vl = Vh + 64 * APAD;

        // ---- S = Q K^T (bf16x3) ----
        float s[8][4];
#pragma unroll
        for (int nt = 0; nt < 8; nt++)
#pragma unroll
            for (int i = 0; i < 4; i++) s[nt][i] = 0.f;

#pragma unroll
        for (int nt = 0; nt < 8; nt++) {
#pragma unroll
            for (int kb2 = 0; kb2 < 4; kb2++) {
                int off = (nt * 8 + g) * APAD + kb2 * 16 + t * 2;
                u32 bh2[2], bl2[2];
                bh2[0] = *(const u32*)&Kh[off];
                bh2[1] = *(const u32*)&Kh[off + 8];
                bl2[0] = *(const u32*)&Kl[off];
                bl2[1] = *(const u32*)&Kl[off + 8];
                mma_bf16(s[nt], qah[kb2], bh2);
                mma_bf16(s[nt], qah[kb2], bl2);
                mma_bf16(s[nt], qal[kb2], bh2);
            }
        }

        // ---- scale (1/sqrt(64) folded here) + causal mask ----
#pragma unroll
        for (int nt = 0; nt < 8; nt++) {
            s[nt][0] *= 0.125f; s[nt][1] *= 0.125f;
            s[nt][2] *= 0.125f; s[nt][3] *= 0.125f;
        }
        if (kt >= 2 * qt) {
            int rg0 = qt * 128 + wq * 16 + g, rg1 = rg0 + 8;
#pragma unroll
            for (int nt = 0; nt < 8; nt++) {
                int cg = kt * 64 + nt * 8 + t * 2;
                if (cg > rg0)     s[nt][0] = -1e30f;
                if (cg + 1 > rg0) s[nt][1] = -1e30f;
                if (cg > rg1)     s[nt][2] = -1e30f;
                if (cg + 1 > rg1) s[nt][3] = -1e30f;
            }
        }

        // ---- online softmax ----
        float tm0 = -1e30f, tm1 = -1e30f;
#pragma unroll
        for (int nt = 0; nt < 8; nt++) {
            tm0 = fmaxf(tm0, fmaxf(s[nt][0], s[nt][1]));
            tm1 = fmaxf(tm1, fmaxf(s[nt][2], s[nt][3]));
        }
        tm0 = fmaxf(tm0, __shfl_xor_sync(0xffffffffu, tm0, 1));
        tm0 = fmaxf(tm0, __shfl_xor_sync(0xffffffffu, tm0, 2));
        tm1 = fmaxf(tm1, __shfl_xor_sync(0xffffffffu, tm1, 1));
        tm1 = fmaxf(tm1, __shfl_xor_sync(0xffffffffu, tm1, 2));

        float mn0 = fmaxf(m0r, tm0), mn1 = fmaxf(m1r, tm1);
        float cf0 = __expf(m0r - mn0), cf1 = __expf(m1r - mn1);
        l0 *= cf0; l1 *= cf1;
#pragma unroll
        for (int nt = 0; nt < 8; nt++) {
            o[nt][0] *= cf0; o[nt][1] *= cf0;
            o[nt][2] *= cf1; o[nt][3] *= cf1;
        }
        m0r = mn0; m1r = mn1;

        float rs0 = 0.f, rs1 = 0.f;
#pragma unroll
        for (int nt = 0; nt < 8; nt++) {
            s[nt][0] = __expf(s[nt][0] - mn0);
            s[nt][1] = __expf(s[nt][1] - mn0);
            s[nt][2] = __expf(s[nt][2] - mn1);
            s[nt][3] = __expf(s[nt][3] - mn1);
            rs0 += s[nt][0] + s[nt][1];
            rs1 += s[nt][2] + s[nt][3];
        }
        rs0 += __shfl_xor_sync(0xffffffffu, rs0, 1);
        rs0 += __shfl_xor_sync(0xffffffffu, rs0, 2);
        rs1 += __shfl_xor_sync(0xffffffffu, rs1, 1);
        rs1 += __shfl_xor_sync(0xffffffffu, rs1, 2);
        l0 += rs0; l1 += rs1;

        // ---- P fragments (register repack, hi/lo) ----
        u32 pah[4][4], pal[4][4];
#pragma unroll
        for (int kb2 = 0; kb2 < 4; kb2++) {
            float* sa = s[2 * kb2];
            float* sb2 = s[2 * kb2 + 1];
            pah[kb2][0] = pk2(sa[0], sa[1]);
            pah[kb2][1] = pk2(sa[2], sa[3]);
            pah[kb2][2] = pk2(sb2[0], sb2[1]);
            pah[kb2][3] = pk2(sb2[2], sb2[3]);
            float la0 = sa[0] - __bfloat162float(__float2bfloat16(sa[0]));
            float la1 = sa[1] - __bfloat162float(__float2bfloat16(sa[1]));
            float la2 = sa[2] - __bfloat162float(__float2bfloat16(sa[2]));
            float la3 = sa[3] - __bfloat162float(__float2bfloat16(sa[3]));
            float lb0 = sb2[0] - __bfloat162float(__float2bfloat16(sb2[0]));
            float lb1 = sb2[1] - __bfloat162float(__float2bfloat16(sb2[1]));
            float lb2 = sb2[2] - __bfloat162float(__float2bfloat16(sb2[2]));
            float lb3 = sb2[3] - __bfloat162float(__float2bfloat16(sb2[3]));
            pal[kb2][0] = pk2(la0, la1);
            pal[kb2][1] = pk2(la2, la3);
            pal[kb2][2] = pk2(lb0, lb1);
            pal[kb2][3] = pk2(lb2, lb3);
        }

        // ---- O += P V (bf16x3) ----
#pragma unroll
        for (int nt = 0; nt < 8; nt++) {
#pragma unroll
            for (int kb2 = 0; kb2 < 4; kb2++) {
                int off = (nt * 8 + g) * APAD + kb2 * 16 + t * 2;
                u32 bh2[2], bl2[2];
                bh2[0] = *(const u32*)&Vh[off];
                bh2[1] = *(const u32*)&Vh[off + 8];
                bl2[0] = *(const u32*)&Vl[off];
                bl2[1] = *(const u32*)&Vl[off + 8];
                mma_bf16(o[nt], pah[kb2], bh2);
                mma_bf16(o[nt], pah[kb2], bl2);
                mma_bf16(o[nt], pal[kb2], bh2);
            }
        }

        __syncthreads();
        if (kt + 2 < nkv) {
            load_kv(kt + 2, kt & 1);
            asm volatile("cp.async.commit_group;\n");
        }
    }

    // ---- normalize + write ctx hi/lo ----
    float inv0 = 1.0f / l0, inv1 = 1.0f / l1;
    int r0 = qt * 128 + wq * 16 + g;
    size_t ob0 = ((size_t)(b * TSEQ + r0)) * CDIM + hh * HD;
    size_t ob1 = ((size_t)(b * TSEQ + r0 + 8)) * CDIM + hh * HD;
#pragma unroll
    for (int nt = 0; nt < 8; nt++) {
        int c = nt * 8 + t * 2;
        float v0 = o[nt][0] * inv0, v1 = o[nt][1] * inv0;
        float v2 = o[nt][2] * inv1, v3 = o[nt][3] * inv1;
        __nv_bfloat16 h0 = __float2bfloat16(v0), h1 = __float2bfloat16(v1);
        __nv_bfloat16 h2 = __float2bfloat16(v2), h3 = __float2bfloat16(v3);
        g_chi[ob0 + c] = h0;     g_chi[ob0 + c + 1] = h1;
        g_chi[ob1 + c] = h2;     g_chi[ob1 + c + 1] = h3;
        g_clo[ob0 + c]     = __float2bfloat16(v0 - __bfloat162float(h0));
        g_clo[ob0 + c + 1] = __float2bfloat16(v1 - __bfloat162float(h1));
        g_clo[ob1 + c]     = __float2bfloat16(v2 - __bfloat162float(h2));
        g_clo[ob1 + c + 1] = __float2bfloat16(v3 - __bfloat162float(h3));
    }
}

// ---------------- log-softmax NLL per row --------------------------------
__global__ __launch_bounds__(256)
void loss_kernel(const float* __restrict__ logits, const int* __restrict__ target) {
    __shared__ float sm[256];
    int row = blockIdx.x;
    const float* lr = logits + (size_t)row * VDIM;
    int tid = threadIdx.x;

    float mx = -1e30f;
    for (int i = tid; i < VDIM; i += 256) mx = fmaxf(mx, lr[i]);
    sm[tid] = mx; __syncthreads();
    for (int s = 128; s > 0; s >>= 1) {
        if (tid < s) sm[tid] = fmaxf(sm[tid], sm[tid + s]);
        __syncthreads();
    }
    mx = sm[0]; __syncthreads();

    float se = 0.f;
    for (int i = tid; i < VDIM; i += 256) se += __expf(lr[i] - mx);
    sm[tid] = se; __syncthreads();
    for (int s = 128; s > 0; s >>= 1) {
        if (tid < s) sm[tid] += sm[tid + s];
        __syncthreads();
    }
    if (tid == 0)
        g_nll[row] = logf(sm[0]) + mx - lr[target[row]];
}

__global__ __launch_bounds__(1024)
void reduce_loss_kernel(float* __restrict__ out, long long loss_idx) {
    __shared__ float sm[1024];
    int tid = threadIdx.x;
    float s = 0.f;
    for (int i = tid; i < BT; i += 1024) s += g_nll[i];
    sm[tid] = s; __syncthreads();
    for (int st = 512; st > 0; st >>= 1) {
        if (tid < st) sm[tid] += sm[tid + st];
        __syncthreads();
    }
    if (tid == 0 && loss_idx >= 0)
        out[loss_idx] = sm[0] / (float)BT;
}

// ---------------- launch --------------------------------------------------
extern "C" void kernel_launch(void* const* d_in, const int* in_sizes, int n_in,
                              void* d_out, int out_size) {
    const int*   x      = (const int*)  d_in[0];
    const int*   target = (const int*)  d_in[1];
    const float* embed_w= (const float*)d_in[2];
    const float* pos    = (const float*)d_in[3];
    const float* Wq     = (const float*)d_in[4];
    const float* bq     = (const float*)d_in[5];
    const float* Wk     = (const float*)d_in[6];
    const float* bk     = (const float*)d_in[7];
    const float* Wv     = (const float*)d_in[8];
    const float* bv     = (const float*)d_in[9];
    const float* Wo     = (const float*)d_in[10];
    const float* bo     = (const float*)d_in[11];
    const float* Wu     = (const float*)d_in[12];
    float* out = (float*)d_out;

    float *h, *logits_scratch;
    cudaGetSymbolAddress((void**)&h, g_h);
    cudaGetSymbolAddress((void**)&logits_scratch, g_logits);

    __nv_bfloat16 *ahi, *alo, *qhi, *qlo, *khi, *klo, *vthi, *vtlo, *chi, *clo;
    __nv_bfloat16 *wqhi, *wqlo, *wkhi, *wklo, *wvhi, *wvlo, *wohi, *wolo, *wuhi, *wulo;
    cudaGetSymbolAddress((void**)&ahi,  g_ahi);  cudaGetSymbolAddress((void**)&alo,  g_alo);
    cudaGetSymbolAddress((void**)&qhi,  g_qhi);  cudaGetSymbolAddress((void**)&qlo,  g_qlo);
    cudaGetSymbolAddress((void**)&khi,  g_khi);  cudaGetSymbolAddress((void**)&klo,  g_klo);
    cudaGetSymbolAddress((void**)&vthi, g_vthi); cudaGetSymbolAddress((void**)&vtlo, g_vtlo);
    cudaGetSymbolAddress((void**)&chi,  g_chi);  cudaGetSymbolAddress((void**)&clo,  g_clo);
    cudaGetSymbolAddress((void**)&wqhi, g_wqhi); cudaGetSymbolAddress((void**)&wqlo, g_wqlo);
    cudaGetSymbolAddress((void**)&wkhi, g_wkhi); cudaGetSymbolAddress((void**)&wklo, g_wklo);
    cudaGetSymbolAddress((void**)&wvhi, g_wvhi); cudaGetSymbolAddress((void**)&wvlo, g_wvlo);
    cudaGetSymbolAddress((void**)&wohi, g_wohi); cudaGetSymbolAddress((void**)&wolo, g_wolo);
    cudaGetSymbolAddress((void**)&wuhi, g_wuhi); cudaGetSymbolAddress((void**)&wulo, g_wulo);

    static bool attr_set = false;
    if (!attr_set) {
        cudaFuncSetAttribute(gemm_bf16x3, cudaFuncAttributeMaxDynamicSharedMemorySize, GSMEM);
        cudaFuncSetAttribute(attn_mma_kernel, cudaFuncAttributeMaxDynamicSharedMemorySize, ASMEM);
        attr_set = true;
    }

    const size_t nlogits = (size_t)BT * VDIM;
    float* logits_dst = ((size_t)out_size >= nlogits) ? out : logits_scratch;
    long long loss_idx;
    if ((size_t)out_size > nlogits)       loss_idx = (long long)nlogits;
    else if ((size_t)out_size < nlogits)  loss_idx = 0;
    else                                  loss_idx = -1;

    // 0) weight splits
    {
        size_t nw = (size_t)LAYERS * CDIM * CDIM;
        unsigned gb = (unsigned)((nw + 255) / 256);
        split_kernel<<<gb, 256>>>(Wq, wqhi, wqlo, nw);
        split_kernel<<<gb, 256>>>(Wk, wkhi, wklo, nw);
        split_kernel<<<gb, 256>>>(Wv, wvhi, wvlo, nw);
        split_kernel<<<gb, 256>>>(Wo, wohi, wolo, nw);
        size_t nu = (size_t)VDIM * CDIM;
        split_kernel<<<(unsigned)((nu + 255) / 256), 256>>>(Wu, wuhi, wulo, nu);
    }

    // 1) embedding + positional (+ hi/lo split of h)
    {
        size_t total = (size_t)BT * CDIM;
        embed_kernel<<<(unsigned)((total + 255) / 256), 256>>>(x, embed_w, pos);
    }

    // 2) transformer layers
    dim3 gC(CDIM / 128, BT / 128);       // (8, 32)
    for (int l = 0; l < LAYERS; l++) {
        size_t woff = (size_t)l * CDIM * CDIM;
        // Q/K: bf16 hi/lo normal layout; V: transposed layout; no fp32 outputs
        gemm_bf16x3<<<gC, GT, GSMEM>>>(ahi, alo, wqhi + woff, wqlo + woff,
                                       bq + l * CDIM, nullptr,
                                       nullptr, qhi, qlo, 0, BT, CDIM, CDIM);
        gemm_bf16x3<<<gC, GT, GSMEM>>>(ahi, alo, wkhi + woff, wklo + woff,
                                       bk + l * CDIM, nullptr,
                                       nullptr, khi, klo, 0, BT, CDIM, CDIM);
        gemm_bf16x3<<<gC, GT, GSMEM>>>(ahi, alo, wvhi + woff, wvlo + woff,
                                       bv + l * CDIM, nullptr,
                                       nullptr, vthi, vtlo, 1, BT, CDIM, CDIM);

        attn_mma_kernel<<<dim3(TSEQ / 128, BATCH * NHEAD), 256, ASMEM>>>();

        // h = ctx @ Wo^T + bo + h ; also write hi/lo split of new h
        gemm_bf16x3<<<gC, GT, GSMEM>>>(chi, clo, wohi + woff, wolo + woff,
                                       bo + l * CDIM, h,
                                       h, ahi, alo, 0, BT, CDIM, CDIM);
    }

    // 3) logits = h @ Wu^T
    gemm_bf16x3<<<dim3(VDIM / 128, BT / 128), GT, GSMEM>>>(ahi, alo, wuhi, wulo,
                                                           nullptr, nullptr,
                                                           logits_dst, nullptr, nullptr,
                                                           0, BT, VDIM, CDIM);

    // 4) loss
    loss_kernel<<<BT, 256>>>(logits_dst, target);
    reduce_loss_kernel<<<1, 1024>>>(out, loss_idx);
}

// round 12
// speedup vs baseline: 3.3955x; 1.0196x over previous
#include <cuda_runtime.h>
#include <cuda_bf16.h>
#include <stdint.h>
#include <math.h>

typedef unsigned int u32;

// ---------------- problem constants (match setup_inputs) ----------------
#define BATCH  2
#define TSEQ   2048
#define CDIM   1024
#define VDIM   8192
#define LAYERS 2
#define NHEAD  16
#define HD     64            // CDIM / NHEAD
#define BT     (BATCH * TSEQ)   // 4096 rows

// ---------------- scratch (device globals: allocation-free) -------------
__device__ float g_h[BT * CDIM];      // hidden state  [B*T, C]
__device__ float g_logits[(size_t)BT * VDIM];
__device__ float g_nll[BT];

// bf16 hi/lo activations
__device__ __nv_bfloat16 g_ahi[BT * CDIM];   // current hidden (GEMM A input)
__device__ __nv_bfloat16 g_alo[BT * CDIM];
__device__ __nv_bfloat16 g_qhi[BT * CDIM];
__device__ __nv_bfloat16 g_qlo[BT * CDIM];
__device__ __nv_bfloat16 g_khi[BT * CDIM];
__device__ __nv_bfloat16 g_klo[BT * CDIM];
__device__ __nv_bfloat16 g_vthi[BT * CDIM];  // transposed: [(b,c)][token]
__device__ __nv_bfloat16 g_vtlo[BT * CDIM];
__device__ __nv_bfloat16 g_chi[BT * CDIM];   // ctx hi/lo
__device__ __nv_bfloat16 g_clo[BT * CDIM];

// bf16 hi/lo weights
__device__ __nv_bfloat16 g_wqhi[LAYERS * CDIM * CDIM];
__device__ __nv_bfloat16 g_wqlo[LAYERS * CDIM * CDIM];
__device__ __nv_bfloat16 g_wkhi[LAYERS * CDIM * CDIM];
__device__ __nv_bfloat16 g_wklo[LAYERS * CDIM * CDIM];
__device__ __nv_bfloat16 g_wvhi[LAYERS * CDIM * CDIM];
__device__ __nv_bfloat16 g_wvlo[LAYERS * CDIM * CDIM];
__device__ __nv_bfloat16 g_wohi[LAYERS * CDIM * CDIM];
__device__ __nv_bfloat16 g_wolo[LAYERS * CDIM * CDIM];
__device__ __nv_bfloat16 g_wuhi[(size_t)VDIM * CDIM];
__device__ __nv_bfloat16 g_wulo[(size_t)VDIM * CDIM];

// ---------------- fp32 -> bf16 hi/lo split (weights only) -----------------
__global__ void split_kernel(const float* __restrict__ src,
                             __nv_bfloat16* __restrict__ hi,
                             __nv_bfloat16* __restrict__ lo, size_t n) {
    size_t i = (size_t)blockIdx.x * blockDim.x + threadIdx.x;
    if (i >= n) return;
    float x = src[i];
    __nv_bfloat16 h = __float2bfloat16(x);
    hi[i] = h;
    lo[i] = __float2bfloat16(x - __bfloat162float(h));
}

// ---------------- embedding + positional (+ hi/lo) ------------------------
__global__ void embed_kernel(const int* __restrict__ x,
                             const float* __restrict__ embed_w,
                             const float* __restrict__ pos) {
    size_t i = (size_t)blockIdx.x * blockDim.x + threadIdx.x;
    size_t total = (size_t)BT * CDIM;
    if (i >= total) return;
    int c  = (int)(i % CDIM);
    size_t bt = i / CDIM;
    int t  = (int)(bt % TSEQ);
    int tok = x[bt];
    float val = embed_w[(size_t)tok * CDIM + c] + pos[(size_t)t * CDIM + c];
    g_h[i] = val;
    __nv_bfloat16 hb = __float2bfloat16(val);
    g_ahi[i] = hb;
    g_alo[i] = __float2bfloat16(val - __bfloat162float(hb));
}

// ---------------- shared helpers ------------------------------------------
__device__ __forceinline__ void cp16(u32 s, const void* g) {
    asm volatile("cp.async.cg.shared.global [%0], [%1], 16;\n" :: "r"(s), "l"(g));
}
__device__ __forceinline__ void mma_bf16(float* d, const u32* a, const u32* b) {
    asm volatile(
        "mma.sync.aligned.m16n8k16.row.col.f32.bf16.bf16.f32 "
        "{%0,%1,%2,%3}, {%4,%5,%6,%7}, {%8,%9}, {%0,%1,%2,%3};\n"
        : "+f"(d[0]), "+f"(d[1]), "+f"(d[2]), "+f"(d[3])
        : "r"(a[0]), "r"(a[1]), "r"(a[2]), "r"(a[3]), "r"(b[0]), "r"(b[1]));
}
__device__ __forceinline__ void ldm4(u32* r, u32 a) {
    asm volatile("ldmatrix.sync.aligned.m8n8.x4.shared.b16 {%0,%1,%2,%3}, [%4];"
                 : "=r"(r[0]), "=r"(r[1]), "=r"(r[2]), "=r"(r[3]) : "r"(a));
}
__device__ __forceinline__ u32 pk2(float x, float y) {
    __nv_bfloat162 p = __floats2bfloat162_rn(x, y);
    return *(u32*)&p;
}

// ---------------- bf16x3 tensor-core GEMM (ldmatrix, 128x128 tile) --------
// out[m,n] = sum_k A[m,k]*W[n,k] (+bias) (+res).
// Passes issued breadth-first (all 16 acc per pass) to break MMA RAW chains;
// per-accumulator summation order unchanged (hh, hl, lh per k-slice).
#define GT 256
#define RS      80                       // padded row bytes (32 bf16 + 8 pad)
#define ARRB    (128 * RS)               // 10240 per array
#define STAGE   (4 * ARRB)               // 40960
#define GSMEM   (2 * STAGE)              // 81920

__global__ __launch_bounds__(GT)
void gemm_bf16x3(const __nv_bfloat16* __restrict__ Ahi, const __nv_bfloat16* __restrict__ Alo,
                 const __nv_bfloat16* __restrict__ Whi, const __nv_bfloat16* __restrict__ Wlo,
                 const float* __restrict__ bias, const float* __restrict__ res,
                 float* __restrict__ outf,
                 __nv_bfloat16* __restrict__ ohi, __nv_bfloat16* __restrict__ olo,
                 int vtrans, int M, int N, int K) {
    extern __shared__ char smraw[];
    u32 sbase = (u32)__cvta_generic_to_shared(smraw);

    int tid = threadIdx.x;
    int lane = tid & 31, wid = tid >> 5;
    int warp_m = wid & 1;
    int warp_n = wid >> 1;
    int m0 = blockIdx.y * 128, n0 = blockIdx.x * 128;
    int g = lane >> 2;
    int t2 = (lane & 3) * 2;

    float acc[4][4][4];
#pragma unroll
    for (int i = 0; i < 4; i++)
#pragma unroll
        for (int j = 0; j < 4; j++)
#pragma unroll
            for (int r = 0; r < 4; r++) acc[i][j][r] = 0.f;

    int NKB = K >> 5;

    auto issue_loads = [&](int kb, int s) {
        int kk = kb << 5;
        u32 st = sbase + s * STAGE;
#pragma unroll
        for (int ii = 0; ii < 8; ii++) {
            int i = tid + ii * GT;
            int arr = i >> 9;
            int rem = i & 511;
            int r = rem >> 2, gg = rem & 3;
            const __nv_bfloat16* src = (arr == 0) ? Ahi : (arr == 1) ? Alo
                                      : (arr == 2) ? Whi : Wlo;
            int row = ((arr < 2) ? m0 : n0) + r;
            u32 dst = st + (u32)arr * ARRB + (u32)(r * RS + gg * 16);
            cp16(dst, src + (size_t)row * K + kk + gg * 8);
        }
    };

    issue_loads(0, 0);
    asm volatile("cp.async.commit_group;\n");
    if (NKB > 1) {
        issue_loads(1, 1);
        asm volatile("cp.async.commit_group;\n");
    }

    for (int kb = 0; kb < NKB; kb++) {
        if (kb + 1 < NKB) asm volatile("cp.async.wait_group 1;\n" ::: "memory");
        else              asm volatile("cp.async.wait_group 0;\n" ::: "memory");
        __syncthreads();

        u32 st = sbase + (kb & 1) * STAGE;

#pragma unroll
        for (int ks = 0; ks < 2; ks++) {
            int kby = ks * 32;

            u32 ah[4][4], al[4][4];
#pragma unroll
            for (int mi = 0; mi < 4; mi++) {
                u32 arow = st + (u32)((warp_m * 64 + mi * 16 + (lane & 15)) * RS
                                      + kby + (lane >> 4) * 16);
                ldm4(ah[mi], arow);
                ldm4(al[mi], arow + ARRB);
            }
            u32 bh[2][4], bl[2][4];
#pragma unroll
            for (int kh = 0; kh < 2; kh++) {
                u32 brow = st + 2 * ARRB + (u32)((warp_n * 32 + lane) * RS
                                                 + kby + kh * 16);
                ldm4(bh[kh], brow);
                ldm4(bl[kh], brow + ARRB);
            }
            u32 bfh[4][2], bfl[4][2];
#pragma unroll
            for (int ni = 0; ni < 4; ni++) {
                bfh[ni][0] = bh[0][ni]; bfh[ni][1] = bh[1][ni];
                bfl[ni][0] = bl[0][ni]; bfl[ni][1] = bl[1][ni];
            }
            // pass 1: hi*hi (16 independent MMAs)
#pragma unroll
            for (int mi = 0; mi < 4; mi++)
#pragma unroll
                for (int ni = 0; ni < 4; ni++)
                    mma_bf16(acc[mi][ni], ah[mi], bfh[ni]);
            // pass 2: hi*lo
#pragma unroll
            for (int mi = 0; mi < 4; mi++)
#pragma unroll
                for (int ni = 0; ni < 4; ni++)
                    mma_bf16(acc[mi][ni], ah[mi], bfl[ni]);
            // pass 3: lo*hi
#pragma unroll
            for (int mi = 0; mi < 4; mi++)
#pragma unroll
                for (int ni = 0; ni < 4; ni++)
                    mma_bf16(acc[mi][ni], al[mi], bfh[ni]);
        }
        __syncthreads();

        if (kb + 2 < NKB) {
            issue_loads(kb + 2, kb & 1);
            asm volatile("cp.async.commit_group;\n");
        }
    }

    // ---- epilogue ----
    auto emit = [&](int m, int cc, float val) {
        if (outf) outf[(size_t)m * N + cc] = val;
        if (ohi) {
            __nv_bfloat16 hb = __float2bfloat16(val);
            __nv_bfloat16 lb = __float2bfloat16(val - __bfloat162float(hb));
            size_t idx = vtrans
                ? ((size_t)((m >> 11) * N + cc)) * TSEQ + (m & 2047)
                : (size_t)m * N + cc;
            ohi[idx] = hb;
            olo[idx] = lb;
        }
    };
#pragma unroll
    for (int mi = 0; mi < 4; mi++) {
        int r0 = m0 + warp_m * 64 + mi * 16 + g;
#pragma unroll
        for (int ni = 0; ni < 4; ni++) {
            int c = n0 + warp_n * 32 + ni * 8 + t2;
            float v0 = acc[mi][ni][0], v1 = acc[mi][ni][1];
            float v2 = acc[mi][ni][2], v3 = acc[mi][ni][3];
            if (bias) { float b0 = bias[c], b1 = bias[c + 1]; v0 += b0; v1 += b1; v2 += b0; v3 += b1; }
            if (res) {
                v0 += res[(size_t)r0 * N + c];       v1 += res[(size_t)r0 * N + c + 1];
                v2 += res[(size_t)(r0 + 8) * N + c]; v3 += res[(size_t)(r0 + 8) * N + c + 1];
            }
            emit(r0, c, v0);     emit(r0, c + 1, v1);
            emit(r0 + 8, c, v2); emit(r0 + 8, c + 1, v3);
        }
    }
}

// ---------------- MMA flash attention (pre-split KV, pipelined) -----------
// CTA: 128 queries (8 warps x 16); KV tiles of 64 keys, double-buffered.
// MMA passes breadth-first over nt (8 independent accs) to break RAW chains.
#define APAD 72
#define QSZB (128 * APAD * 2)
#define KSZB (64 * APAD * 2)
#define STGB (4 * KSZB)
#define ASMEM (2 * QSZB + 2 * STGB)  // 110592

__global__ __launch_bounds__(256)
void attn_mma_kernel() {
    extern __shared__ char araw[];
    u32 sb = (u32)__cvta_generic_to_shared(araw);
    __nv_bfloat16* Qh = (__nv_bfloat16*)araw;
    __nv_bfloat16* Ql = Qh + 128 * APAD;

    int tid = threadIdx.x, lane = tid & 31, wq = tid >> 5;
    int g = lane >> 2, t = lane & 3;
    int b = blockIdx.y >> 4, hh = blockIdx.y & 15;
    int qt = (int)(gridDim.x - 1 - blockIdx.x);
    int nkv = 2 * qt + 2;

    {
        size_t qb = ((size_t)(b * TSEQ + qt * 128)) * CDIM + hh * HD;
#pragma unroll
        for (int ii = 0; ii < 8; ii++) {
            int i = tid + ii * 256;
            int arr = i >> 10, rem = i & 1023;
            int r = rem >> 3, gg = rem & 7;
            const __nv_bfloat16* src = (arr ? g_qlo : g_qhi) + qb + (size_t)r * CDIM + gg * 8;
            cp16(sb + (u32)arr * QSZB + (u32)(r * (APAD * 2) + gg * 16), src);
        }
    }
    auto load_kv = [&](int kt, int st) {
        u32 base = sb + 2 * QSZB + (u32)st * STGB;
        size_t kb = ((size_t)(b * TSEQ + kt * 64)) * CDIM + hh * HD;
        size_t vb = ((size_t)(b * CDIM + hh * HD)) * TSEQ + kt * 64;
#pragma unroll
        for (int ii = 0; ii < 8; ii++) {
            int i = tid + ii * 256;
            int arr = i >> 9, rem = i & 511;
            int r = rem >> 3, gg = rem & 7;
            const __nv_bfloat16* src;
            if (arr == 0)      src = g_khi  + kb + (size_t)r * CDIM + gg * 8;
            else if (arr == 1) src = g_klo  + kb + (size_t)r * CDIM + gg * 8;
            else if (arr == 2) src = g_vthi + vb + (size_t)r * TSEQ + gg * 8;
            else               src = g_vtlo + vb + (size_t)r * TSEQ + gg * 8;
            cp16(base + (u32)arr * KSZB + (u32)(r * (APAD * 2) + gg * 16), src);
        }
    };
    load_kv(0, 0);
    asm volatile("cp.async.commit_group;\n");
    load_kv(1, 1);
    asm volatile("cp.async.commit_group;\n");

    u32 qah[4][4], qal[4][4];
    float m0r = -1e30f, m1r = -1e30f, l0 = 0.f, l1 = 0.f;
    float o[8][4];
#pragma unroll
    for (int nt = 0; nt < 8; nt++)
#pragma unroll
        for (int i = 0; i < 4; i++) o[nt][i] = 0.f;

    for (int kt = 0; kt < nkv; kt++) {
        if (kt + 1 < nkv) asm volatile("cp.async.wait_group 1;\n" ::: "memory");
        else              asm volatile("cp.async.wait_group 0;\n" ::: "memory");
        __syncthreads();

        if (kt == 0) {
#pragma unroll
            for (int kb2 = 0; kb2 < 4; kb2++) {
                int r = wq * 16 + g, kk = kb2 * 16 + t * 2;
                qah[kb2][0] = *(const u32*)&Qh[r * APAD + kk];
                qah[kb2][1] = *(const u32*)&Qh[(r + 8) * APAD + kk];
                qah[kb2][2] = *(const u32*)&Qh[r * APAD + kk + 8];
                qah[kb2][3] = *(const u32*)&Qh[(r + 8) * APAD + kk + 8];
                qal[kb2][0] = *(const u32*)&Ql[r * APAD + kk];
                qal[kb2][1] = *(const u32*)&Ql[(r + 8) * APAD + kk];
                qal[kb2][2] = *(const u32*)&Ql[r * APAD + kk + 8];
                qal[kb2][3] = *(const u32*)&Ql[(r + 8) * APAD + kk + 8];
            }
        }

        __nv_bfloat16* Kh = (__nv_bfloat16*)(araw + 2 * QSZB + (kt & 1) * STGB);
        __nv_bfloat16* Kl = Kh + 64 * APAD;
        __nv_bfloat16* Vh = Kl + 64 * APAD;
        __nv_bfloat16* Vl = Vh + 64 * APAD;

        // ---- S = Q K^T (bf16x3, breadth-first per kb2) ----
        float s[8][4];
#pragma unroll
        for (int nt = 0; nt < 8; nt++)
#pragma unroll
            for (int i = 0; i < 4; i++) s[nt][i] = 0.f;

#pragma unroll
        for (int kb2 = 0; kb2 < 4; kb2++) {
            u32 kh2[8][2], kl2[8][2];
#pragma unroll
            for (int nt = 0; nt < 8; nt++) {
                int off = (nt * 8 + g) * APAD + kb2 * 16 + t * 2;
                kh2[nt][0] = *(const u32*)&Kh[off];
                kh2[nt][1] = *(const u32*)&Kh[off + 8];
                kl2[nt][0] = *(const u32*)&Kl[off];
                kl2[nt][1] = *(const u32*)&Kl[off + 8];
            }
#pragma unroll
            for (int nt = 0; nt < 8; nt++) mma_bf16(s[nt], qah[kb2], kh2[nt]);
#pragma unroll
            for (int nt = 0; nt < 8; nt++) mma_bf16(s[nt], qah[kb2], kl2[nt]);
#pragma unroll
            for (int nt = 0; nt < 8; nt++) mma_bf16(s[nt], qal[kb2], kh2[nt]);
        }

        // ---- scale + causal mask ----
#pragma unroll
        for (int nt = 0; nt < 8; nt++) {
            s[nt][0] *= 0.125f; s[nt][1] *= 0.125f;
            s[nt][2] *= 0.125f; s[nt][3] *= 0.125f;
        }
        if (kt >= 2 * qt) {
            int rg0 = qt * 128 + wq * 16 + g, rg1 = rg0 + 8;
#pragma unroll
            for (int nt = 0; nt < 8; nt++) {
                int cg = kt * 64 + nt * 8 + t * 2;
                if (cg > rg0)     s[nt][0] = -1e30f;
                if (cg + 1 > rg0) s[nt][1] = -1e30f;
                if (cg > rg1)     s[nt][2] = -1e30f;
                if (cg + 1 > rg1) s[nt][3] = -1e30f;
            }
        }

        // ---- online softmax ----
        float tm0 = -1e30f, tm1 = -1e30f;
#pragma unroll
        for (int nt = 0; nt < 8; nt++) {
            tm0 = fmaxf(tm0, fmaxf(s[nt][0], s[nt][1]));
            tm1 = fmaxf(tm1, fmaxf(s[nt][2], s[nt][3]));
        }
        tm0 = fmaxf(tm0, __shfl_xor_sync(0xffffffffu, tm0, 1));
        tm0 = fmaxf(tm0, __shfl_xor_sync(0xffffffffu, tm0, 2));
        tm1 = fmaxf(tm1, __shfl_xor_sync(0xffffffffu, tm1, 1));
        tm1 = fmaxf(tm1, __shfl_xor_sync(0xffffffffu, tm1, 2));

        float mn0 = fmaxf(m0r, tm0), mn1 = fmaxf(m1r, tm1);
        float cf0 = __expf(m0r - mn0), cf1 = __expf(m1r - mn1);
        l0 *= cf0; l1 *= cf1;
#pragma unroll
        for (int nt = 0; nt < 8; nt++) {
            o[nt][0] *= cf0; o[nt][1] *= cf0;
            o[nt][2] *= cf1; o[nt][3] *= cf1;
        }
        m0r = mn0; m1r = mn1;

        float rs0 = 0.f, rs1 = 0.f;
#pragma unroll
        for (int nt = 0; nt < 8; nt++) {
            s[nt][0] = __expf(s[nt][0] - mn0);
            s[nt][1] = __expf(s[nt][1] - mn0);
            s[nt][2] = __expf(s[nt][2] - mn1);
            s[nt][3] = __expf(s[nt][3] - mn1);
            rs0 += s[nt][0] + s[nt][1];
            rs1 += s[nt][2] + s[nt][3];
        }
        rs0 += __shfl_xor_sync(0xffffffffu, rs0, 1);
        rs0 += __shfl_xor_sync(0xffffffffu, rs0, 2);
        rs1 += __shfl_xor_sync(0xffffffffu, rs1, 1);
        rs1 += __shfl_xor_sync(0xffffffffu, rs1, 2);
        l0 += rs0; l1 += rs1;

        // ---- P fragments (register repack, hi/lo) ----
        u32 pah[4][4], pal[4][4];
#pragma unroll
        for (int kb2 = 0; kb2 < 4; kb2++) {
            float* sa = s[2 * kb2];
            float* sb2 = s[2 * kb2 + 1];
            pah[kb2][0] = pk2(sa[0], sa[1]);
            pah[kb2][1] = pk2(sa[2], sa[3]);
            pah[kb2][2] = pk2(sb2[0], sb2[1]);
            pah[kb2][3] = pk2(sb2[2], sb2[3]);
            float la0 = sa[0] - __bfloat162float(__float2bfloat16(sa[0]));
            float la1 = sa[1] - __bfloat162float(__float2bfloat16(sa[1]));
            float la2 = sa[2] - __bfloat162float(__float2bfloat16(sa[2]));
            float la3 = sa[3] - __bfloat162float(__float2bfloat16(sa[3]));
            float lb0 = sb2[0] - __bfloat162float(__float2bfloat16(sb2[0]));
            float lb1 = sb2[1] - __bfloat162float(__float2bfloat16(sb2[1]));
            float lb2 = sb2[2] - __bfloat162float(__float2bfloat16(sb2[2]));
            float lb3 = sb2[3] - __bfloat162float(__float2bfloat16(sb2[3]));
            pal[kb2][0] = pk2(la0, la1);
            pal[kb2][1] = pk2(la2, la3);
            pal[kb2][2] = pk2(lb0, lb1);
            pal[kb2][3] = pk2(lb2, lb3);
        }

        // ---- O += P V (bf16x3, breadth-first per kb2) ----
#pragma unroll
        for (int kb2 = 0; kb2 < 4; kb2++) {
            u32 vh2[8][2], vl2[8][2];
#pragma unroll
            for (int nt = 0; nt < 8; nt++) {
                int off = (nt * 8 + g) * APAD + kb2 * 16 + t * 2;
                vh2[nt][0] = *(const u32*)&Vh[off];
                vh2[nt][1] = *(const u32*)&Vh[off + 8];
                vl2[nt][0] = *(const u32*)&Vl[off];
                vl2[nt][1] = *(const u32*)&Vl[off + 8];
            }
#pragma unroll
            for (int nt = 0; nt < 8; nt++) mma_bf16(o[nt], pah[kb2], vh2[nt]);
#pragma unroll
            for (int nt = 0; nt < 8; nt++) mma_bf16(o[nt], pah[kb2], vl2[nt]);
#pragma unroll
            for (int nt = 0; nt < 8; nt++) mma_bf16(o[nt], pal[kb2], vh2[nt]);
        }

        __syncthreads();
        if (kt + 2 < nkv) {
            load_kv(kt + 2, kt & 1);
            asm volatile("cp.async.commit_group;\n");
        }
    }

    // ---- normalize + write ctx hi/lo ----
    float inv0 = 1.0f / l0, inv1 = 1.0f / l1;
    int r0 = qt * 128 + wq * 16 + g;
    size_t ob0 = ((size_t)(b * TSEQ + r0)) * CDIM + hh * HD;
    size_t ob1 = ((size_t)(b * TSEQ + r0 + 8)) * CDIM + hh * HD;
#pragma unroll
    for (int nt = 0; nt < 8; nt++) {
        int c = nt * 8 + t * 2;
        float v0 = o[nt][0] * inv0, v1 = o[nt][1] * inv0;
        float v2 = o[nt][2] * inv1, v3 = o[nt][3] * inv1;
        __nv_bfloat16 h0 = __float2bfloat16(v0), h1 = __float2bfloat16(v1);
        __nv_bfloat16 h2 = __float2bfloat16(v2), h3 = __float2bfloat16(v3);
        g_chi[ob0 + c] = h0;     g_chi[ob0 + c + 1] = h1;
        g_chi[ob1 + c] = h2;     g_chi[ob1 + c + 1] = h3;
        g_clo[ob0 + c]     = __float2bfloat16(v0 - __bfloat162float(h0));
        g_clo[ob0 + c + 1] = __float2bfloat16(v1 - __bfloat162float(h1));
        g_clo[ob1 + c]     = __float2bfloat16(v2 - __bfloat162float(h2));
        g_clo[ob1 + c + 1] = __float2bfloat16(v3 - __bfloat162float(h3));
    }
}

// ---------------- log-softmax NLL per row --------------------------------
__global__ __launch_bounds__(256)
void loss_kernel(const float* __restrict__ logits, const int* __restrict__ target) {
    __shared__ float sm[256];
    int row = blockIdx.x;
    const float* lr = logits + (size_t)row * VDIM;
    int tid = threadIdx.x;

    float mx = -1e30f;
    for (int i = tid; i < VDIM; i += 256) mx = fmaxf(mx, lr[i]);
    sm[tid] = mx; __syncthreads();
    for (int s = 128; s > 0; s >>= 1) {
        if (tid < s) sm[tid] = fmaxf(sm[tid], sm[tid + s]);
        __syncthreads();
    }
    mx = sm[0]; __syncthreads();

    float se = 0.f;
    for (int i = tid; i < VDIM; i += 256) se += __expf(lr[i] - mx);
    sm[tid] = se; __syncthreads();
    for (int s = 128; s > 0; s >>= 1) {
        if (tid < s) sm[tid] += sm[tid + s];
        __syncthreads();
    }
    if (tid == 0)
        g_nll[row] = logf(sm[0]) + mx - lr[target[row]];
}

__global__ __launch_bounds__(1024)
void reduce_loss_kernel(float* __restrict__ out, long long loss_idx) {
    __shared__ float sm[1024];
    int tid = threadIdx.x;
    float s = 0.f;
    for (int i = tid; i < BT; i += 1024) s += g_nll[i];
    sm[tid] = s; __syncthreads();
    for (int st = 512; st > 0; st >>= 1) {
        if (tid < st) sm[tid] += sm[tid + st];
        __syncthreads();
    }
    if (tid == 0 && loss_idx >= 0)
        out[loss_idx] = sm[0] / (float)BT;
}

// ---------------- launch --------------------------------------------------
extern "C" void kernel_launch(void* const* d_in, const int* in_sizes, int n_in,
                              void* d_out, int out_size) {
    const int*   x      = (const int*)  d_in[0];
    const int*   target = (const int*)  d_in[1];
    const float* embed_w= (const float*)d_in[2];
    const float* pos    = (const float*)d_in[3];
    const float* Wq     = (const float*)d_in[4];
    const float* bq     = (const float*)d_in[5];
    const float* Wk     = (const float*)d_in[6];
    const float* bk     = (const float*)d_in[7];
    const float* Wv     = (const float*)d_in[8];
    const float* bv     = (const float*)d_in[9];
    const float* Wo     = (const float*)d_in[10];
    const float* bo     = (const float*)d_in[11];
    const float* Wu     = (const float*)d_in[12];
    float* out = (float*)d_out;

    float *h, *logits_scratch;
    cudaGetSymbolAddress((void**)&h, g_h);
    cudaGetSymbolAddress((void**)&logits_scratch, g_logits);

    __nv_bfloat16 *ahi, *alo, *qhi, *qlo, *khi, *klo, *vthi, *vtlo, *chi, *clo;
    __nv_bfloat16 *wqhi, *wqlo, *wkhi, *wklo, *wvhi, *wvlo, *wohi, *wolo, *wuhi, *wulo;
    cudaGetSymbolAddress((void**)&ahi,  g_ahi);  cudaGetSymbolAddress((void**)&alo,  g_alo);
    cudaGetSymbolAddress((void**)&qhi,  g_qhi);  cudaGetSymbolAddress((void**)&qlo,  g_qlo);
    cudaGetSymbolAddress((void**)&khi,  g_khi);  cudaGetSymbolAddress((void**)&klo,  g_klo);
    cudaGetSymbolAddress((void**)&vthi, g_vthi); cudaGetSymbolAddress((void**)&vtlo, g_vtlo);
    cudaGetSymbolAddress((void**)&chi,  g_chi);  cudaGetSymbolAddress((void**)&clo,  g_clo);
    cudaGetSymbolAddress((void**)&wqhi, g_wqhi); cudaGetSymbolAddress((void**)&wqlo, g_wqlo);
    cudaGetSymbolAddress((void**)&wkhi, g_wkhi); cudaGetSymbolAddress((void**)&wklo, g_wklo);
    cudaGetSymbolAddress((void**)&wvhi, g_wvhi); cudaGetSymbolAddress((void**)&wvlo, g_wvlo);
    cudaGetSymbolAddress((void**)&wohi, g_wohi); cudaGetSymbolAddress((void**)&wolo, g_wolo);
    cudaGetSymbolAddress((void**)&wuhi, g_wuhi); cudaGetSymbolAddress((void**)&wulo, g_wulo);

    static bool attr_set = false;
    if (!attr_set) {
        cudaFuncSetAttribute(gemm_bf16x3, cudaFuncAttributeMaxDynamicSharedMemorySize, GSMEM);
        cudaFuncSetAttribute(attn_mma_kernel, cudaFuncAttributeMaxDynamicSharedMemorySize, ASMEM);
        attr_set = true;
    }

    const size_t nlogits = (size_t)BT * VDIM;
    float* logits_dst = ((size_t)out_size >= nlogits) ? out : logits_scratch;
    long long loss_idx;
    if ((size_t)out_size > nlogits)       loss_idx = (long long)nlogits;
    else if ((size_t)out_size < nlogits)  loss_idx = 0;
    else                                  loss_idx = -1;

    // 0) weight splits
    {
        size_t nw = (size_t)LAYERS * CDIM * CDIM;
        unsigned gb = (unsigned)((nw + 255) / 256);
        split_kernel<<<gb, 256>>>(Wq, wqhi, wqlo, nw);
        split_kernel<<<gb, 256>>>(Wk, wkhi, wklo, nw);
        split_kernel<<<gb, 256>>>(Wv, wvhi, wvlo, nw);
        split_kernel<<<gb, 256>>>(Wo, wohi, wolo, nw);
        size_t nu = (size_t)VDIM * CDIM;
        split_kernel<<<(unsigned)((nu + 255) / 256), 256>>>(Wu, wuhi, wulo, nu);
    }

    // 1) embedding + positional (+ hi/lo split of h)
    {
        size_t total = (size_t)BT * CDIM;
        embed_kernel<<<(unsigned)((total + 255) / 256), 256>>>(x, embed_w, pos);
    }

    // 2) transformer layers
    dim3 gC(CDIM / 128, BT / 128);       // (8, 32)
    for (int l = 0; l < LAYERS; l++) {
        size_t woff = (size_t)l * CDIM * CDIM;
        gemm_bf16x3<<<gC, GT, GSMEM>>>(ahi, alo, wqhi + woff, wqlo + woff,
                                       bq + l * CDIM, nullptr,
                                       nullptr, qhi, qlo, 0, BT, CDIM, CDIM);
        gemm_bf16x3<<<gC, GT, GSMEM>>>(ahi, alo, wkhi + woff, wklo + woff,
                                       bk + l * CDIM, nullptr,
                                       nullptr, khi, klo, 0, BT, CDIM, CDIM);
        gemm_bf16x3<<<gC, GT, GSMEM>>>(ahi, alo, wvhi + woff, wvlo + woff,
                                       bv + l * CDIM, nullptr,
                                       nullptr, vthi, vtlo, 1, BT, CDIM, CDIM);

        attn_mma_kernel<<<dim3(TSEQ / 128, BATCH * NHEAD), 256, ASMEM>>>();

        gemm_bf16x3<<<gC, GT, GSMEM>>>(chi, clo, wohi + woff, wolo + woff,
                                       bo + l * CDIM, h,
                                       h, ahi, alo, 0, BT, CDIM, CDIM);
    }

    // 3) logits = h @ Wu^T
    gemm_bf16x3<<<dim3(VDIM / 128, BT / 128), GT, GSMEM>>>(ahi, alo, wuhi, wulo,
                                                           nullptr, nullptr,
                                                           logits_dst, nullptr, nullptr,
                                                           0, BT, VDIM, CDIM);

    // 4) loss
    loss_kernel<<<BT, 256>>>(logits_dst, target);
    reduce_loss_kernel<<<1, 1024>>>(out, loss_idx);
}

// round 13
// speedup vs baseline: 3.5340x; 1.0408x over previous
#include <cuda_runtime.h>
#include <cuda_bf16.h>
#include <stdint.h>
#include <math.h>

typedef unsigned int u32;

// ---------------- problem constants (match setup_inputs) ----------------
#define BATCH  2
#define TSEQ   2048
#define CDIM   1024
#define VDIM   8192
#define LAYERS 2
#define NHEAD  16
#define HD     64
#define BT     (BATCH * TSEQ)   // 4096 rows

// ---------------- scratch (device globals: allocation-free) -------------
__device__ float g_h[BT * CDIM];
__device__ float g_logits[(size_t)BT * VDIM];
__device__ float g_nll[BT];

__device__ __nv_bfloat16 g_ahi[BT * CDIM];
__device__ __nv_bfloat16 g_alo[BT * CDIM];
__device__ __nv_bfloat16 g_qhi[BT * CDIM];
__device__ __nv_bfloat16 g_qlo[BT * CDIM];
__device__ __nv_bfloat16 g_khi[BT * CDIM];
__device__ __nv_bfloat16 g_klo[BT * CDIM];
__device__ __nv_bfloat16 g_vthi[BT * CDIM];  // transposed: [(b,c)][token]
__device__ __nv_bfloat16 g_vtlo[BT * CDIM];
__device__ __nv_bfloat16 g_chi[BT * CDIM];
__device__ __nv_bfloat16 g_clo[BT * CDIM];

__device__ __nv_bfloat16 g_wqhi[LAYERS * CDIM * CDIM];
__device__ __nv_bfloat16 g_wqlo[LAYERS * CDIM * CDIM];
__device__ __nv_bfloat16 g_wkhi[LAYERS * CDIM * CDIM];
__device__ __nv_bfloat16 g_wklo[LAYERS * CDIM * CDIM];
__device__ __nv_bfloat16 g_wvhi[LAYERS * CDIM * CDIM];
__device__ __nv_bfloat16 g_wvlo[LAYERS * CDIM * CDIM];
__device__ __nv_bfloat16 g_wohi[LAYERS * CDIM * CDIM];
__device__ __nv_bfloat16 g_wolo[LAYERS * CDIM * CDIM];
__device__ __nv_bfloat16 g_wuhi[(size_t)VDIM * CDIM];
__device__ __nv_bfloat16 g_wulo[(size_t)VDIM * CDIM];

// ---------------- fp32 -> bf16 hi/lo split (weights) ----------------------
__global__ void split_kernel(const float* __restrict__ src,
                             __nv_bfloat16* __restrict__ hi,
                             __nv_bfloat16* __restrict__ lo, size_t n) {
    size_t i = (size_t)blockIdx.x * blockDim.x + threadIdx.x;
    if (i >= n) return;
    float x = src[i];
    __nv_bfloat16 h = __float2bfloat16(x);
    hi[i] = h;
    lo[i] = __float2bfloat16(x - __bfloat162float(h));
}

// ---------------- embedding + positional (+ hi/lo) ------------------------
__global__ void embed_kernel(const int* __restrict__ x,
                             const float* __restrict__ embed_w,
                             const float* __restrict__ pos) {
    size_t i = (size_t)blockIdx.x * blockDim.x + threadIdx.x;
    size_t total = (size_t)BT * CDIM;
    if (i >= total) return;
    int c  = (int)(i % CDIM);
    size_t bt = i / CDIM;
    int t  = (int)(bt % TSEQ);
    int tok = x[bt];
    float val = embed_w[(size_t)tok * CDIM + c] + pos[(size_t)t * CDIM + c];
    g_h[i] = val;
    __nv_bfloat16 hb = __float2bfloat16(val);
    g_ahi[i] = hb;
    g_alo[i] = __float2bfloat16(val - __bfloat162float(hb));
}

// ---------------- shared helpers ------------------------------------------
__device__ __forceinline__ void cp16(u32 s, const void* g) {
    asm volatile("cp.async.cg.shared.global [%0], [%1], 16;\n" :: "r"(s), "l"(g));
}
__device__ __forceinline__ void mma_bf16(float* d, const u32* a, const u32* b) {
    asm volatile(
        "mma.sync.aligned.m16n8k16.row.col.f32.bf16.bf16.f32 "
        "{%0,%1,%2,%3}, {%4,%5,%6,%7}, {%8,%9}, {%0,%1,%2,%3};\n"
        : "+f"(d[0]), "+f"(d[1]), "+f"(d[2]), "+f"(d[3])
        : "r"(a[0]), "r"(a[1]), "r"(a[2]), "r"(a[3]), "r"(b[0]), "r"(b[1]));
}
__device__ __forceinline__ void ldm4(u32* r, u32 a) {
    asm volatile("ldmatrix.sync.aligned.m8n8.x4.shared.b16 {%0,%1,%2,%3}, [%4];"
                 : "=r"(r[0]), "=r"(r[1]), "=r"(r[2]), "=r"(r[3]) : "r"(a));
}
__device__ __forceinline__ u32 pk2(float x, float y) {
    __nv_bfloat162 p = __floats2bfloat162_rn(x, y);
    return *(u32*)&p;
}

// ---------------- GEMM tile config ----------------------------------------
#define GT 256
#define RS      80
#define ARRB    (128 * RS)
#define STAGE   (4 * ARRB)
#define GSMEM   (2 * STAGE)              // 81920

// Shared mainloop body as a macro-free device function pattern:
// (kept inline in each kernel for clarity; both copies identical)

// ---------------- fused QKV GEMM ------------------------------------------
struct QKVArgs {
    const __nv_bfloat16 *Ahi, *Alo;
    const __nv_bfloat16 *Wh[3], *Wl[3];
    const float *bias[3];
    __nv_bfloat16 *ohi[3], *olo[3];
};

__global__ __launch_bounds__(GT)
void gemm_qkv(QKVArgs args) {
    extern __shared__ char smraw[];
    u32 sbase = (u32)__cvta_generic_to_shared(smraw);

    int tid = threadIdx.x;
    int lane = tid & 31, wid = tid >> 5;
    int warp_m = wid & 1, warp_n = wid >> 1;
    int wsel = (int)(blockIdx.x >> 3);          // 0:Q 1:K 2:V
    int m0 = blockIdx.y * 128, n0 = (int)(blockIdx.x & 7) * 128;
    int g = lane >> 2, t2 = (lane & 3) * 2;
    const int N = CDIM, K = CDIM;

    const __nv_bfloat16* Ahi = args.Ahi;
    const __nv_bfloat16* Alo = args.Alo;
    const __nv_bfloat16* Whi = args.Wh[wsel];
    const __nv_bfloat16* Wlo = args.Wl[wsel];

    float acc[4][4][4];
#pragma unroll
    for (int i = 0; i < 4; i++)
#pragma unroll
        for (int j = 0; j < 4; j++)
#pragma unroll
            for (int r = 0; r < 4; r++) acc[i][j][r] = 0.f;

    int NKB = K >> 5;
    auto issue_loads = [&](int kb, int s) {
        int kk = kb << 5;
        u32 st = sbase + s * STAGE;
#pragma unroll
        for (int ii = 0; ii < 8; ii++) {
            int i = tid + ii * GT;
            int arr = i >> 9, rem = i & 511;
            int r = rem >> 2, gg = rem & 3;
            const __nv_bfloat16* src = (arr == 0) ? Ahi : (arr == 1) ? Alo
                                      : (arr == 2) ? Whi : Wlo;
            int row = ((arr < 2) ? m0 : n0) + r;
            u32 dst = st + (u32)arr * ARRB + (u32)(r * RS + gg * 16);
            cp16(dst, src + (size_t)row * K + kk + gg * 8);
        }
    };

    issue_loads(0, 0);
    asm volatile("cp.async.commit_group;\n");
    issue_loads(1, 1);
    asm volatile("cp.async.commit_group;\n");

    for (int kb = 0; kb < NKB; kb++) {
        if (kb + 1 < NKB) asm volatile("cp.async.wait_group 1;\n" ::: "memory");
        else              asm volatile("cp.async.wait_group 0;\n" ::: "memory");
        __syncthreads();
        u32 st = sbase + (kb & 1) * STAGE;

#pragma unroll
        for (int ks = 0; ks < 2; ks++) {
            int kby = ks * 32;
            u32 ah[4][4], al[4][4];
#pragma unroll
            for (int mi = 0; mi < 4; mi++) {
                u32 arow = st + (u32)((warp_m * 64 + mi * 16 + (lane & 15)) * RS
                                      + kby + (lane >> 4) * 16);
                ldm4(ah[mi], arow);
                ldm4(al[mi], arow + ARRB);
            }
            u32 bh[2][4], bl[2][4];
#pragma unroll
            for (int kh = 0; kh < 2; kh++) {
                u32 brow = st + 2 * ARRB + (u32)((warp_n * 32 + lane) * RS
                                                 + kby + kh * 16);
                ldm4(bh[kh], brow);
                ldm4(bl[kh], brow + ARRB);
            }
            u32 bfh[4][2], bfl[4][2];
#pragma unroll
            for (int ni = 0; ni < 4; ni++) {
                bfh[ni][0] = bh[0][ni]; bfh[ni][1] = bh[1][ni];
                bfl[ni][0] = bl[0][ni]; bfl[ni][1] = bl[1][ni];
            }
#pragma unroll
            for (int mi = 0; mi < 4; mi++)
#pragma unroll
                for (int ni = 0; ni < 4; ni++)
                    mma_bf16(acc[mi][ni], ah[mi], bfh[ni]);
#pragma unroll
            for (int mi = 0; mi < 4; mi++)
#pragma unroll
                for (int ni = 0; ni < 4; ni++)
                    mma_bf16(acc[mi][ni], ah[mi], bfl[ni]);
#pragma unroll
            for (int mi = 0; mi < 4; mi++)
#pragma unroll
                for (int ni = 0; ni < 4; ni++)
                    mma_bf16(acc[mi][ni], al[mi], bfh[ni]);
        }
        __syncthreads();
        if (kb + 2 < NKB) {
            issue_loads(kb + 2, kb & 1);
            asm volatile("cp.async.commit_group;\n");
        }
    }

    const float* bias = args.bias[wsel];
    __nv_bfloat16* ohi = args.ohi[wsel];
    __nv_bfloat16* olo = args.olo[wsel];
    int vtrans = (wsel == 2);

    auto emit = [&](int m, int cc, float val) {
        __nv_bfloat16 hb = __float2bfloat16(val);
        __nv_bfloat16 lb = __float2bfloat16(val - __bfloat162float(hb));
        size_t idx = vtrans
            ? ((size_t)((m >> 11) * N + cc)) * TSEQ + (m & 2047)
            : (size_t)m * N + cc;
        ohi[idx] = hb;
        olo[idx] = lb;
    };
#pragma unroll
    for (int mi = 0; mi < 4; mi++) {
        int r0 = m0 + warp_m * 64 + mi * 16 + g;
#pragma unroll
        for (int ni = 0; ni < 4; ni++) {
            int c = n0 + warp_n * 32 + ni * 8 + t2;
            float b0 = bias[c], b1 = bias[c + 1];
            emit(r0, c, acc[mi][ni][0] + b0);
            emit(r0, c + 1, acc[mi][ni][1] + b1);
            emit(r0 + 8, c, acc[mi][ni][2] + b0);
            emit(r0 + 8, c + 1, acc[mi][ni][3] + b1);
        }
    }
}

// ---------------- generic bf16x3 GEMM (Wo, logits) -------------------------
__global__ __launch_bounds__(GT)
void gemm_bf16x3(const __nv_bfloat16* __restrict__ Ahi, const __nv_bfloat16* __restrict__ Alo,
                 const __nv_bfloat16* __restrict__ Whi, const __nv_bfloat16* __restrict__ Wlo,
                 const float* __restrict__ bias, const float* __restrict__ res,
                 float* __restrict__ outf,
                 __nv_bfloat16* __restrict__ ohi, __nv_bfloat16* __restrict__ olo,
                 int M, int N, int K) {
    extern __shared__ char smraw[];
    u32 sbase = (u32)__cvta_generic_to_shared(smraw);

    int tid = threadIdx.x;
    int lane = tid & 31, wid = tid >> 5;
    int warp_m = wid & 1, warp_n = wid >> 1;
    int m0 = blockIdx.y * 128, n0 = blockIdx.x * 128;
    int g = lane >> 2, t2 = (lane & 3) * 2;

    float acc[4][4][4];
#pragma unroll
    for (int i = 0; i < 4; i++)
#pragma unroll
        for (int j = 0; j < 4; j++)
#pragma unroll
            for (int r = 0; r < 4; r++) acc[i][j][r] = 0.f;

    int NKB = K >> 5;
    auto issue_loads = [&](int kb, int s) {
        int kk = kb << 5;
        u32 st = sbase + s * STAGE;
#pragma unroll
        for (int ii = 0; ii < 8; ii++) {
            int i = tid + ii * GT;
            int arr = i >> 9, rem = i & 511;
            int r = rem >> 2, gg = rem & 3;
            const __nv_bfloat16* src = (arr == 0) ? Ahi : (arr == 1) ? Alo
                                      : (arr == 2) ? Whi : Wlo;
            int row = ((arr < 2) ? m0 : n0) + r;
            u32 dst = st + (u32)arr * ARRB + (u32)(r * RS + gg * 16);
            cp16(dst, src + (size_t)row * K + kk + gg * 8);
        }
    };

    issue_loads(0, 0);
    asm volatile("cp.async.commit_group;\n");
    issue_loads(1, 1);
    asm volatile("cp.async.commit_group;\n");

    for (int kb = 0; kb < NKB; kb++) {
        if (kb + 1 < NKB) asm volatile("cp.async.wait_group 1;\n" ::: "memory");
        else              asm volatile("cp.async.wait_group 0;\n" ::: "memory");
        __syncthreads();
        u32 st = sbase + (kb & 1) * STAGE;

#pragma unroll
        for (int ks = 0; ks < 2; ks++) {
            int kby = ks * 32;
            u32 ah[4][4], al[4][4];
#pragma unroll
            for (int mi = 0; mi < 4; mi++) {
                u32 arow = st + (u32)((warp_m * 64 + mi * 16 + (lane & 15)) * RS
                                      + kby + (lane >> 4) * 16);
                ldm4(ah[mi], arow);
                ldm4(al[mi], arow + ARRB);
            }
            u32 bh[2][4], bl[2][4];
#pragma unroll
            for (int kh = 0; kh < 2; kh++) {
                u32 brow = st + 2 * ARRB + (u32)((warp_n * 32 + lane) * RS
                                                 + kby + kh * 16);
                ldm4(bh[kh], brow);
                ldm4(bl[kh], brow + ARRB);
            }
            u32 bfh[4][2], bfl[4][2];
#pragma unroll
            for (int ni = 0; ni < 4; ni++) {
                bfh[ni][0] = bh[0][ni]; bfh[ni][1] = bh[1][ni];
                bfl[ni][0] = bl[0][ni]; bfl[ni][1] = bl[1][ni];
            }
#pragma unroll
            for (int mi = 0; mi < 4; mi++)
#pragma unroll
                for (int ni = 0; ni < 4; ni++)
                    mma_bf16(acc[mi][ni], ah[mi], bfh[ni]);
#pragma unroll
            for (int mi = 0; mi < 4; mi++)
#pragma unroll
                for (int ni = 0; ni < 4; ni++)
                    mma_bf16(acc[mi][ni], ah[mi], bfl[ni]);
#pragma unroll
            for (int mi = 0; mi < 4; mi++)
#pragma unroll
                for (int ni = 0; ni < 4; ni++)
                    mma_bf16(acc[mi][ni], al[mi], bfh[ni]);
        }
        __syncthreads();
        if (kb + 2 < NKB) {
            issue_loads(kb + 2, kb & 1);
            asm volatile("cp.async.commit_group;\n");
        }
    }

    auto emit = [&](int m, int cc, float val) {
        if (outf) outf[(size_t)m * N + cc] = val;
        if (ohi) {
            __nv_bfloat16 hb = __float2bfloat16(val);
            __nv_bfloat16 lb = __float2bfloat16(val - __bfloat162float(hb));
            size_t idx = (size_t)m * N + cc;
            ohi[idx] = hb;
            olo[idx] = lb;
        }
    };
#pragma unroll
    for (int mi = 0; mi < 4; mi++) {
        int r0 = m0 + warp_m * 64 + mi * 16 + g;
#pragma unroll
        for (int ni = 0; ni < 4; ni++) {
            int c = n0 + warp_n * 32 + ni * 8 + t2;
            float v0 = acc[mi][ni][0], v1 = acc[mi][ni][1];
            float v2 = acc[mi][ni][2], v3 = acc[mi][ni][3];
            if (bias) { float b0 = bias[c], b1 = bias[c + 1]; v0 += b0; v1 += b1; v2 += b0; v3 += b1; }
            if (res) {
                v0 += res[(size_t)r0 * N + c];       v1 += res[(size_t)r0 * N + c + 1];
                v2 += res[(size_t)(r0 + 8) * N + c]; v3 += res[(size_t)(r0 + 8) * N + c + 1];
            }
            emit(r0, c, v0);     emit(r0, c + 1, v1);
            emit(r0 + 8, c, v2); emit(r0 + 8, c + 1, v3);
        }
    }
}

// ---------------- MMA flash attention -------------------------------------
#define APAD 72
#define QSZB (128 * APAD * 2)
#define KSZB (64 * APAD * 2)
#define STGB (4 * KSZB)
#define ASMEM (2 * QSZB + 2 * STGB)  // 110592

__global__ __launch_bounds__(256)
void attn_mma_kernel() {
    extern __shared__ char araw[];
    u32 sb = (u32)__cvta_generic_to_shared(araw);
    __nv_bfloat16* Qh = (__nv_bfloat16*)araw;
    __nv_bfloat16* Ql = Qh + 128 * APAD;

    int tid = threadIdx.x, lane = tid & 31, wq = tid >> 5;
    int g = lane >> 2, t = lane & 3;
    int b = blockIdx.y >> 4, hh = blockIdx.y & 15;
    int qt = (int)(gridDim.x - 1 - blockIdx.x);
    int nkv = 2 * qt + 2;

    {
        size_t qb = ((size_t)(b * TSEQ + qt * 128)) * CDIM + hh * HD;
#pragma unroll
        for (int ii = 0; ii < 8; ii++) {
            int i = tid + ii * 256;
            int arr = i >> 10, rem = i & 1023;
            int r = rem >> 3, gg = rem & 7;
            const __nv_bfloat16* src = (arr ? g_qlo : g_qhi) + qb + (size_t)r * CDIM + gg * 8;
            cp16(sb + (u32)arr * QSZB + (u32)(r * (APAD * 2) + gg * 16), src);
        }
    }
    auto load_kv = [&](int kt, int st) {
        u32 base = sb + 2 * QSZB + (u32)st * STGB;
        size_t kb = ((size_t)(b * TSEQ + kt * 64)) * CDIM + hh * HD;
        size_t vb = ((size_t)(b * CDIM + hh * HD)) * TSEQ + kt * 64;
#pragma unroll
        for (int ii = 0; ii < 8; ii++) {
            int i = tid + ii * 256;
            int arr = i >> 9, rem = i & 511;
            int r = rem >> 3, gg = rem & 7;
            const __nv_bfloat16* src;
            if (arr == 0)      src = g_khi  + kb + (size_t)r * CDIM + gg * 8;
            else if (arr == 1) src = g_klo  + kb + (size_t)r * CDIM + gg * 8;
            else if (arr == 2) src = g_vthi + vb + (size_t)r * TSEQ + gg * 8;
            else               src = g_vtlo + vb + (size_t)r * TSEQ + gg * 8;
            cp16(base + (u32)arr * KSZB + (u32)(r * (APAD * 2) + gg * 16), src);
        }
    };
    load_kv(0, 0);
    asm volatile("cp.async.commit_group;\n");
    load_kv(1, 1);
    asm volatile("cp.async.commit_group;\n");

    u32 qah[4][4], qal[4][4];
    float m0r = -1e30f, m1r = -1e30f, l0 = 0.f, l1 = 0.f;
    float o[8][4];
#pragma unroll
    for (int nt = 0; nt < 8; nt++)
#pragma unroll
        for (int i = 0; i < 4; i++) o[nt][i] = 0.f;

    for (int kt = 0; kt < nkv; kt++) {
        if (kt + 1 < nkv) asm volatile("cp.async.wait_group 1;\n" ::: "memory");
        else              asm volatile("cp.async.wait_group 0;\n" ::: "memory");
        __syncthreads();

        if (kt == 0) {
#pragma unroll
            for (int kb2 = 0; kb2 < 4; kb2++) {
                int r = wq * 16 + g, kk = kb2 * 16 + t * 2;
                qah[kb2][0] = *(const u32*)&Qh[r * APAD + kk];
                qah[kb2][1] = *(const u32*)&Qh[(r + 8) * APAD + kk];
                qah[kb2][2] = *(const u32*)&Qh[r * APAD + kk + 8];
                qah[kb2][3] = *(const u32*)&Qh[(r + 8) * APAD + kk + 8];
                qal[kb2][0] = *(const u32*)&Ql[r * APAD + kk];
                qal[kb2][1] = *(const u32*)&Ql[(r + 8) * APAD + kk];
                qal[kb2][2] = *(const u32*)&Ql[r * APAD + kk + 8];
                qal[kb2][3] = *(const u32*)&Ql[(r + 8) * APAD + kk + 8];
            }
        }

        __nv_bfloat16* Kh = (__nv_bfloat16*)(araw + 2 * QSZB + (kt & 1) * STGB);
        __nv_bfloat16* Kl = Kh + 64 * APAD;
        __nv_bfloat16* Vh = Kl + 64 * APAD;
        __nv_bfloat16* Vl = Vh + 64 * APAD;

        float s[8][4];
#pragma unroll
        for (int nt = 0; nt < 8; nt++)
#pragma unroll
            for (int i = 0; i < 4; i++) s[nt][i] = 0.f;

#pragma unroll
        for (int kb2 = 0; kb2 < 4; kb2++) {
            u32 kh2[8][2], kl2[8][2];
#pragma unroll
            for (int nt = 0; nt < 8; nt++) {
                int off = (nt * 8 + g) * APAD + kb2 * 16 + t * 2;
                kh2[nt][0] = *(const u32*)&Kh[off];
                kh2[nt][1] = *(const u32*)&Kh[off + 8];
                kl2[nt][0] = *(const u32*)&Kl[off];
                kl2[nt][1] = *(const u32*)&Kl[off + 8];
            }
#pragma unroll
            for (int nt = 0; nt < 8; nt++) mma_bf16(s[nt], qah[kb2], kh2[nt]);
#pragma unroll
            for (int nt = 0; nt < 8; nt++) mma_bf16(s[nt], qah[kb2], kl2[nt]);
#pragma unroll
            for (int nt = 0; nt < 8; nt++) mma_bf16(s[nt], qal[kb2], kh2[nt]);
        }

#pragma unroll
        for (int nt = 0; nt < 8; nt++) {
            s[nt][0] *= 0.125f; s[nt][1] *= 0.125f;
            s[nt][2] *= 0.125f; s[nt][3] *= 0.125f;
        }
        if (kt >= 2 * qt) {
            int rg0 = qt * 128 + wq * 16 + g, rg1 = rg0 + 8;
#pragma unroll
            for (int nt = 0; nt < 8; nt++) {
                int cg = kt * 64 + nt * 8 + t * 2;
                if (cg > rg0)     s[nt][0] = -1e30f;
                if (cg + 1 > rg0) s[nt][1] = -1e30f;
                if (cg > rg1)     s[nt][2] = -1e30f;
                if (cg + 1 > rg1) s[nt][3] = -1e30f;
            }
        }

        float tm0 = -1e30f, tm1 = -1e30f;
#pragma unroll
        for (int nt = 0; nt < 8; nt++) {
            tm0 = fmaxf(tm0, fmaxf(s[nt][0], s[nt][1]));
            tm1 = fmaxf(tm1, fmaxf(s[nt][2], s[nt][3]));
        }
        tm0 = fmaxf(tm0, __shfl_xor_sync(0xffffffffu, tm0, 1));
        tm0 = fmaxf(tm0, __shfl_xor_sync(0xffffffffu, tm0, 2));
        tm1 = fmaxf(tm1, __shfl_xor_sync(0xffffffffu, tm1, 1));
        tm1 = fmaxf(tm1, __shfl_xor_sync(0xffffffffu, tm1, 2));

        float mn0 = fmaxf(m0r, tm0), mn1 = fmaxf(m1r, tm1);
        float cf0 = __expf(m0r - mn0), cf1 = __expf(m1r - mn1);
        l0 *= cf0; l1 *= cf1;
#pragma unroll
        for (int nt = 0; nt < 8; nt++) {
            o[nt][0] *= cf0; o[nt][1] *= cf0;
            o[nt][2] *= cf1; o[nt][3] *= cf1;
        }
        m0r = mn0; m1r = mn1;

        float rs0 = 0.f, rs1 = 0.f;
#pragma unroll
        for (int nt = 0; nt < 8; nt++) {
            s[nt][0] = __expf(s[nt][0] - mn0);
            s[nt][1] = __expf(s[nt][1] - mn0);
            s[nt][2] = __expf(s[nt][2] - mn1);
            s[nt][3] = __expf(s[nt][3] - mn1);
            rs0 += s[nt][0] + s[nt][1];
            rs1 += s[nt][2] + s[nt][3];
        }
        rs0 += __shfl_xor_sync(0xffffffffu, rs0, 1);
        rs0 += __shfl_xor_sync(0xffffffffu, rs0, 2);
        rs1 += __shfl_xor_sync(0xffffffffu, rs1, 1);
        rs1 += __shfl_xor_sync(0xffffffffu, rs1, 2);
        l0 += rs0; l1 += rs1;

        // ---- P fragments (hi only; P >= 0, |p_lo| <= 2^-9 p — lo pass dropped) ----
        u32 pah[4][4];
#pragma unroll
        for (int kb2 = 0; kb2 < 4; kb2++) {
            float* sa = s[2 * kb2];
            float* sb2 = s[2 * kb2 + 1];
            pah[kb2][0] = pk2(sa[0], sa[1]);
            pah[kb2][1] = pk2(sa[2], sa[3]);
            pah[kb2][2] = pk2(sb2[0], sb2[1]);
            pah[kb2][3] = pk2(sb2[2], sb2[3]);
        }

        // ---- O += P V (2-pass: ph*vh + ph*vl) ----
#pragma unroll
        for (int kb2 = 0; kb2 < 4; kb2++) {
            u32 vh2[8][2], vl2[8][2];
#pragma unroll
            for (int nt = 0; nt < 8; nt++) {
                int off = (nt * 8 + g) * APAD + kb2 * 16 + t * 2;
                vh2[nt][0] = *(const u32*)&Vh[off];
                vh2[nt][1] = *(const u32*)&Vh[off + 8];
                vl2[nt][0] = *(const u32*)&Vl[off];
                vl2[nt][1] = *(const u32*)&Vl[off + 8];
            }
#pragma unroll
            for (int nt = 0; nt < 8; nt++) mma_bf16(o[nt], pah[kb2], vh2[nt]);
#pragma unroll
            for (int nt = 0; nt < 8; nt++) mma_bf16(o[nt], pah[kb2], vl2[nt]);
        }

        __syncthreads();
        if (kt + 2 < nkv) {
            load_kv(kt + 2, kt & 1);
            asm volatile("cp.async.commit_group;\n");
        }
    }

    float inv0 = 1.0f / l0, inv1 = 1.0f / l1;
    int r0 = qt * 128 + wq * 16 + g;
    size_t ob0 = ((size_t)(b * TSEQ + r0)) * CDIM + hh * HD;
    size_t ob1 = ((size_t)(b * TSEQ + r0 + 8)) * CDIM + hh * HD;
#pragma unroll
    for (int nt = 0; nt < 8; nt++) {
        int c = nt * 8 + t * 2;
        float v0 = o[nt][0] * inv0, v1 = o[nt][1] * inv0;
        float v2 = o[nt][2] * inv1, v3 = o[nt][3] * inv1;
        __nv_bfloat16 h0 = __float2bfloat16(v0), h1 = __float2bfloat16(v1);
        __nv_bfloat16 h2 = __float2bfloat16(v2), h3 = __float2bfloat16(v3);
        g_chi[ob0 + c] = h0;     g_chi[ob0 + c + 1] = h1;
        g_chi[ob1 + c] = h2;     g_chi[ob1 + c + 1] = h3;
        g_clo[ob0 + c]     = __float2bfloat16(v0 - __bfloat162float(h0));
        g_clo[ob0 + c + 1] = __float2bfloat16(v1 - __bfloat162float(h1));
        g_clo[ob1 + c]     = __float2bfloat16(v2 - __bfloat162float(h2));
        g_clo[ob1 + c + 1] = __float2bfloat16(v3 - __bfloat162float(h3));
    }
}

// ---------------- log-softmax NLL per row (vectorized) --------------------
__global__ __launch_bounds__(256)
void loss_kernel(const float* __restrict__ logits, const int* __restrict__ target) {
    __shared__ float sm[8];
    int row = blockIdx.x;
    const float4* lr4 = (const float4*)(logits + (size_t)row * VDIM);
    int tid = threadIdx.x, lane = tid & 31, warp = tid >> 5;

    float mx = -1e30f;
#pragma unroll
    for (int it = 0; it < 8; it++) {
        float4 v = lr4[tid + it * 256];
        mx = fmaxf(mx, fmaxf(fmaxf(v.x, v.y), fmaxf(v.z, v.w)));
    }
#pragma unroll
    for (int d = 16; d > 0; d >>= 1) mx = fmaxf(mx, __shfl_xor_sync(0xffffffffu, mx, d));
    if (lane == 0) sm[warp] = mx;
    __syncthreads();
    mx = fmaxf(fmaxf(fmaxf(sm[0], sm[1]), fmaxf(sm[2], sm[3])),
               fmaxf(fmaxf(sm[4], sm[5]), fmaxf(sm[6], sm[7])));
    __syncthreads();

    float se = 0.f;
#pragma unroll
    for (int it = 0; it < 8; it++) {
        float4 v = lr4[tid + it * 256];
        se += __expf(v.x - mx) + __expf(v.y - mx) + __expf(v.z - mx) + __expf(v.w - mx);
    }
#pragma unroll
    for (int d = 16; d > 0; d >>= 1) se += __shfl_xor_sync(0xffffffffu, se, d);
    if (lane == 0) sm[warp] = se;
    __syncthreads();
    if (tid == 0) {
        float tot = sm[0] + sm[1] + sm[2] + sm[3] + sm[4] + sm[5] + sm[6] + sm[7];
        g_nll[row] = logf(tot) + mx - logits[(size_t)row * VDIM + target[row]];
    }
}

__global__ __launch_bounds__(1024)
void reduce_loss_kernel(float* __restrict__ out, long long loss_idx) {
    __shared__ float sm[1024];
    int tid = threadIdx.x;
    float s = 0.f;
    for (int i = tid; i < BT; i += 1024) s += g_nll[i];
    sm[tid] = s; __syncthreads();
    for (int st = 512; st > 0; st >>= 1) {
        if (tid < st) sm[tid] += sm[tid + st];
        __syncthreads();
    }
    if (tid == 0 && loss_idx >= 0)
        out[loss_idx] = sm[0] / (float)BT;
}

// ---------------- launch --------------------------------------------------
extern "C" void kernel_launch(void* const* d_in, const int* in_sizes, int n_in,
                              void* d_out, int out_size) {
    const int*   x      = (const int*)  d_in[0];
    const int*   target = (const int*)  d_in[1];
    const float* embed_w= (const float*)d_in[2];
    const float* pos    = (const float*)d_in[3];
    const float* Wq     = (const float*)d_in[4];
    const float* bq     = (const float*)d_in[5];
    const float* Wk     = (const float*)d_in[6];
    const float* bk     = (const float*)d_in[7];
    const float* Wv     = (const float*)d_in[8];
    const float* bv     = (const float*)d_in[9];
    const float* Wo     = (const float*)d_in[10];
    const float* bo     = (const float*)d_in[11];
    const float* Wu     = (const float*)d_in[12];
    float* out = (float*)d_out;

    float *h, *logits_scratch;
    cudaGetSymbolAddress((void**)&h, g_h);
    cudaGetSymbolAddress((void**)&logits_scratch, g_logits);

    __nv_bfloat16 *ahi, *alo, *qhi, *qlo, *khi, *klo, *vthi, *vtlo, *chi, *clo;
    __nv_bfloat16 *wqhi, *wqlo, *wkhi, *wklo, *wvhi, *wvlo, *wohi, *wolo, *wuhi, *wulo;
    cudaGetSymbolAddress((void**)&ahi,  g_ahi);  cudaGetSymbolAddress((void**)&alo,  g_alo);
    cudaGetSymbolAddress((void**)&qhi,  g_qhi);  cudaGetSymbolAddress((void**)&qlo,  g_qlo);
    cudaGetSymbolAddress((void**)&khi,  g_khi);  cudaGetSymbolAddress((void**)&klo,  g_klo);
    cudaGetSymbolAddress((void**)&vthi, g_vthi); cudaGetSymbolAddress((void**)&vtlo, g_vtlo);
    cudaGetSymbolAddress((void**)&chi,  g_chi);  cudaGetSymbolAddress((void**)&clo,  g_clo);
    cudaGetSymbolAddress((void**)&wqhi, g_wqhi); cudaGetSymbolAddress((void**)&wqlo, g_wqlo);
    cudaGetSymbolAddress((void**)&wkhi, g_wkhi); cudaGetSymbolAddress((void**)&wklo, g_wklo);
    cudaGetSymbolAddress((void**)&wvhi, g_wvhi); cudaGetSymbolAddress((void**)&wvlo, g_wvlo);
    cudaGetSymbolAddress((void**)&wohi, g_wohi); cudaGetSymbolAddress((void**)&wolo, g_wolo);
    cudaGetSymbolAddress((void**)&wuhi, g_wuhi); cudaGetSymbolAddress((void**)&wulo, g_wulo);

    static bool attr_set = false;
    if (!attr_set) {
        cudaFuncSetAttribute(gemm_bf16x3, cudaFuncAttributeMaxDynamicSharedMemorySize, GSMEM);
        cudaFuncSetAttribute(gemm_qkv, cudaFuncAttributeMaxDynamicSharedMemorySize, GSMEM);
        cudaFuncSetAttribute(attn_mma_kernel, cudaFuncAttributeMaxDynamicSharedMemorySize, ASMEM);
        attr_set = true;
    }

    const size_t nlogits = (size_t)BT * VDIM;
    float* logits_dst = ((size_t)out_size >= nlogits) ? out : logits_scratch;
    long long loss_idx;
    if ((size_t)out_size > nlogits)       loss_idx = (long long)nlogits;
    else if ((size_t)out_size < nlogits)  loss_idx = 0;
    else                                  loss_idx = -1;

    // 0) weight splits
    {
        size_t nw = (size_t)LAYERS * CDIM * CDIM;
        unsigned gb = (unsigned)((nw + 255) / 256);
        split_kernel<<<gb, 256>>>(Wq, wqhi, wqlo, nw);
        split_kernel<<<gb, 256>>>(Wk, wkhi, wklo, nw);
        split_kernel<<<gb, 256>>>(Wv, wvhi, wvlo, nw);
        split_kernel<<<gb, 256>>>(Wo, wohi, wolo, nw);
        size_t nu = (size_t)VDIM * CDIM;
        split_kernel<<<(unsigned)((nu + 255) / 256), 256>>>(Wu, wuhi, wulo, nu);
    }

    // 1) embedding
    {
        size_t total = (size_t)BT * CDIM;
        embed_kernel<<<(unsigned)((total + 255) / 256), 256>>>(x, embed_w, pos);
    }

    // 2) transformer layers
    dim3 gC(CDIM / 128, BT / 128);       // (8, 32)
    dim3 gQKV(3 * CDIM / 128, BT / 128); // (24, 32)
    for (int l = 0; l < LAYERS; l++) {
        size_t woff = (size_t)l * CDIM * CDIM;
        QKVArgs qa;
        qa.Ahi = ahi; qa.Alo = alo;
        qa.Wh[0] = wqhi + woff; qa.Wl[0] = wqlo + woff;
        qa.Wh[1] = wkhi + woff; qa.Wl[1] = wklo + woff;
        qa.Wh[2] = wvhi + woff; qa.Wl[2] = wvlo + woff;
        qa.bias[0] = bq + l * CDIM; qa.bias[1] = bk + l * CDIM; qa.bias[2] = bv + l * CDIM;
        qa.ohi[0] = qhi;  qa.olo[0] = qlo;
        qa.ohi[1] = khi;  qa.olo[1] = klo;
        qa.ohi[2] = vthi; qa.olo[2] = vtlo;
        gemm_qkv<<<gQKV, GT, GSMEM>>>(qa);

        attn_mma_kernel<<<dim3(TSEQ / 128, BATCH * NHEAD), 256, ASMEM>>>();

        gemm_bf16x3<<<gC, GT, GSMEM>>>(chi, clo, wohi + woff, wolo + woff,
                                       bo + l * CDIM, h,
                                       h, ahi, alo, BT, CDIM, CDIM);
    }

    // 3) logits = h @ Wu^T
    gemm_bf16x3<<<dim3(VDIM / 128, BT / 128), GT, GSMEM>>>(ahi, alo, wuhi, wulo,
                                                           nullptr, nullptr,
                                                           logits_dst, nullptr, nullptr,
                                                           BT, VDIM, CDIM);

    // 4) loss
    loss_kernel<<<BT, 256>>>(logits_dst, target);
    reduce_loss_kernel<<<1, 1024>>>(out, loss_idx);
}